// round 11
// baseline (speedup 1.0000x reference)
#include <cuda_runtime.h>
#include <cuda_fp16.h>
#include <math.h>
#include <stdint.h>

// Problem constants
#define D     512
#define NHEAD 16
#define HS    32
#define NB    64
#define MAXN  128
#define ATT_SCALE 0.17677669529663687f
#define LN_EPS 1e-5f
#define MAX_ROWS 8192
#define WELEM (512 * 512)

// Scratch
__device__ float g_y[MAX_ROWS * D];
__device__ int   g_starts[NB + 1];
__device__ __half g_whi[4 * WELEM];
__device__ __half g_wlo[4 * WELEM];
__device__ __half g_ahi[MAX_ROWS * D];
__device__ __half g_alo[MAX_ROWS * D];
__device__ __half g_qhi[MAX_ROWS * D];
__device__ __half g_qlo[MAX_ROWS * D];
__device__ __half g_khi[MAX_ROWS * D];
__device__ __half g_klo[MAX_ROWS * D];
__device__ __half g_vhi[MAX_ROWS * D];
__device__ __half g_vlo[MAX_ROWS * D];

#define SWZ128(o) ((o) ^ (((o) >> 3) & 0x70u))
#define SWZ256(o) ((o) ^ (((o) >> 4) & 0x70u))

__device__ __forceinline__ uint32_t smem_to_u32(const void* p) {
    uint32_t a;
    asm("{ .reg .u64 t; cvta.to.shared.u64 t, %1; cvt.u32.u64 %0, t; }"
        : "=r"(a) : "l"(p));
    return a;
}
__device__ __forceinline__ void ldsm4(uint32_t* r, uint32_t addr) {
    asm volatile("ldmatrix.sync.aligned.m8n8.x4.shared.b16 {%0,%1,%2,%3}, [%4];"
                 : "=r"(r[0]), "=r"(r[1]), "=r"(r[2]), "=r"(r[3]) : "r"(addr));
}
// NOTE: non-volatile — register-only op, lets ptxas schedule around ldsm.
__device__ __forceinline__ void mma16816(float* c, const uint32_t* a,
                                         const uint32_t* b) {
    asm("mma.sync.aligned.m16n8k16.row.col.f32.f16.f16.f32 "
        "{%0,%1,%2,%3}, {%4,%5,%6,%7}, {%8,%9}, {%0,%1,%2,%3};"
        : "+f"(c[0]), "+f"(c[1]), "+f"(c[2]), "+f"(c[3])
        : "r"(a[0]), "r"(a[1]), "r"(a[2]), "r"(a[3]), "r"(b[0]), "r"(b[1]));
}
__device__ __forceinline__ uint32_t packh(__half a, __half b) {
    __half2 h = __halves2half2(a, b);
    return *reinterpret_cast<uint32_t*>(&h);
}
__device__ __forceinline__ void split2(float x, __half& hi, __half& lo) {
    hi = __float2half_rn(x);
    lo = __float2half_rn(x - __half2float(hi));
}
__device__ __forceinline__ void cp_async16(uint32_t dst, const void* src, int sz) {
    asm volatile("cp.async.cg.shared.global [%0], [%1], 16, %2;"
                 :: "r"(dst), "l"(src), "r"(sz) : "memory");
}
#define CP_COMMIT() asm volatile("cp.async.commit_group;" ::: "memory")
#define CP_WAIT(n)  asm volatile("cp.async.wait_group %0;" :: "n"(n) : "memory")

// ---------------------------------------------------------------------------
// split kernels
// ---------------------------------------------------------------------------
__global__ void split_w_kernel(const float* __restrict__ Wq,
                               const float* __restrict__ Wk,
                               const float* __restrict__ Wv,
                               const float* __restrict__ Wp) {
    int i = blockIdx.x * blockDim.x + threadIdx.x;
    int i4 = i * 4;
    if (i4 >= 4 * WELEM) return;
    int w = i4 >> 18;
    int off = i4 & (WELEM - 1);
    const float* src = (w == 0) ? Wq : (w == 1) ? Wk : (w == 2) ? Wv : Wp;
    float4 v = *reinterpret_cast<const float4*>(&src[off]);
    __half hx, hy, hz, hw, lx, ly, lz, lw;
    split2(v.x, hx, lx); split2(v.y, hy, ly);
    split2(v.z, hz, lz); split2(v.w, hw, lw);
    uint2 hi, lo;
    hi.x = packh(hx, hy); hi.y = packh(hz, hw);
    lo.x = packh(lx, ly); lo.y = packh(lz, lw);
    reinterpret_cast<uint2*>(g_whi)[i] = hi;
    reinterpret_cast<uint2*>(g_wlo)[i] = lo;
}

__global__ void split_rows_kernel(const float* __restrict__ src, int n4) {
    int i = blockIdx.x * blockDim.x + threadIdx.x;
    if (i >= n4) return;
    float4 v = reinterpret_cast<const float4*>(src)[i];
    __half hx, hy, hz, hw, lx, ly, lz, lw;
    split2(v.x, hx, lx); split2(v.y, hy, ly);
    split2(v.z, hz, lz); split2(v.w, hw, lw);
    uint2 hi, lo;
    hi.x = packh(hx, hy); hi.y = packh(hz, hw);
    lo.x = packh(lx, ly); lo.y = packh(lz, lw);
    reinterpret_cast<uint2*>(g_ahi)[i] = hi;
    reinterpret_cast<uint2*>(g_alo)[i] = lo;
}

// ---------------------------------------------------------------------------
// split-fp16 (3-term) mma.sync GEMM.
// Block tile BM x 256, 512 thr = 16 warps (4m x 4n), warp tile (BM/4) x 64.
// cp.async staging, 3-stage circular buffer; B-fragment ldsm double-buffered
// across np to cover LDSM latency with mma issue.
// ---------------------------------------------------------------------------
#define GBK 32
#define NSTAGE (D / GBK)

template <int BM, int HOUT>
__global__ void __launch_bounds__(512, 1)
mma_gemm(const __half* __restrict__ Ahi, const __half* __restrict__ Alo,
         const __half* __restrict__ Whi, const __half* __restrict__ Wlo,
         int wstride,
         const float* __restrict__ b0, const float* __restrict__ b1,
         const float* __restrict__ b2,
         float* __restrict__ o0,
         __half* __restrict__ oh0, __half* __restrict__ ol0,
         __half* __restrict__ oh1, __half* __restrict__ ol1,
         __half* __restrict__ oh2, __half* __restrict__ ol2,
         const float* __restrict__ resid, int M) {
    constexpr int MF = BM / 64;
    constexpr int ABYTES = BM * 128;
    constexpr int BBYTES = 256 * 128;
    constexpr int BUF = ABYTES + BBYTES;
    constexpr int A_ITER = (ABYTES / 16) / 512;
    extern __shared__ __align__(128) char smem[];
    uint32_t sbase = smem_to_u32(smem);
    int tid = threadIdx.x;
    int lane = tid & 31;
    int wid = tid >> 5;
    int warp_m = wid & 3;
    int warp_n = wid >> 2;
    int bm = blockIdx.x * BM;
    int ntile = blockIdx.y;
    int wsel = ntile >> 1;
    const __half* WH = Whi + (size_t)wsel * wstride;
    const __half* WL = Wlo + (size_t)wsel * wstride;
    const float* bias = (wsel == 0) ? b0 : (wsel == 1 ? b1 : b2);
    __half* OutHi = (wsel == 0) ? oh0 : (wsel == 1 ? oh1 : oh2);
    __half* OutLo = (wsel == 0) ? ol0 : (wsel == 1 ? ol1 : ol2);
    int nbase = (ntile & 1) * 256;

    auto stage = [&](int s, int d) {
        int k0 = s * GBK;
        uint32_t base = sbase + d * BUF;
#pragma unroll
        for (int j = 0; j < A_ITER; j++) {
            int c = tid + j * 512;
            int row = c >> 3, sub = c & 7, plane = sub >> 2, i = sub & 3;
            uint32_t dst = base + SWZ128((uint32_t)(row * 128 + plane * 64 + i * 16));
            const __half* sp = plane ? Alo : Ahi;
            int gr = bm + row;
            const __half* src = sp + (size_t)gr * D + k0 + i * 8;
            cp_async16(dst, src, gr < M ? 16 : 0);
        }
#pragma unroll
        for (int j = 0; j < 4; j++) {
            int c = tid + j * 512;
            int row = c >> 3, sub = c & 7, plane = sub >> 2, i = sub & 3;
            uint32_t dst = base + ABYTES +
                           SWZ128((uint32_t)(row * 128 + plane * 64 + i * 16));
            const __half* sp = plane ? WL : WH;
            const __half* src = sp + (size_t)(nbase + row) * D + k0 + i * 8;
            cp_async16(dst, src, 16);
        }
        CP_COMMIT();
    };

    float acc[MF][8][4];
#pragma unroll
    for (int i = 0; i < MF; i++)
#pragma unroll
        for (int j = 0; j < 8; j++)
#pragma unroll
            for (int k = 0; k < 4; k++) acc[i][j][k] = 0.f;

    stage(0, 0);
    stage(1, 1);

    for (int s = 0; s < NSTAGE; s++) {
        if (s == NSTAGE - 1) CP_WAIT(0); else CP_WAIT(1);
        __syncthreads();
        if (s + 2 < NSTAGE) stage(s + 2, (s + 2) % 3);

        uint32_t Abase = sbase + (s % 3) * BUF;
        uint32_t Bbase = Abase + ABYTES;
#pragma unroll
        for (int ks = 0; ks < 2; ks++) {
            uint32_t ah[MF][4], al[MF][4];
#pragma unroll
            for (int mf = 0; mf < MF; mf++) {
                int row = warp_m * (16 * MF) + mf * 16 + (lane & 15);
                uint32_t off =
                    (uint32_t)(row * 128 + ks * 32 + ((lane >> 4) << 4));
                ldsm4(ah[mf], Abase + SWZ128(off));
                ldsm4(al[mf], Abase + SWZ128(off + 64));
            }
            // B fragments: double-buffered across np
            uint32_t rh[2][4], rl[2][4];
            {
                int g = lane >> 3;
                int n = warp_n * 64 + ((g >> 1) << 3) + (lane & 7);
                uint32_t off = (uint32_t)(n * 128 + ks * 32 + ((g & 1) << 4));
                ldsm4(rh[0], Bbase + SWZ128(off));
                ldsm4(rl[0], Bbase + SWZ128(off + 64));
            }
#pragma unroll
            for (int np = 0; np < 4; np++) {
                int cur = np & 1;
                if (np < 3) {
                    int g = lane >> 3;
                    int n = warp_n * 64 + (np + 1) * 16 + ((g >> 1) << 3) + (lane & 7);
                    uint32_t off = (uint32_t)(n * 128 + ks * 32 + ((g & 1) << 4));
                    ldsm4(rh[cur ^ 1], Bbase + SWZ128(off));
                    ldsm4(rl[cur ^ 1], Bbase + SWZ128(off + 64));
                }
#pragma unroll
                for (int mf = 0; mf < MF; mf++) {
                    mma16816(acc[mf][np * 2], ah[mf], rh[cur]);
                    mma16816(acc[mf][np * 2 + 1], ah[mf], rh[cur] + 2);
                    mma16816(acc[mf][np * 2], ah[mf], rl[cur]);
                    mma16816(acc[mf][np * 2 + 1], ah[mf], rl[cur] + 2);
                    mma16816(acc[mf][np * 2], al[mf], rh[cur]);
                    mma16816(acc[mf][np * 2 + 1], al[mf], rh[cur] + 2);
                }
            }
        }
    }

    // ---- epilogue
#pragma unroll
    for (int mf = 0; mf < MF; mf++) {
#pragma unroll
        for (int nf = 0; nf < 8; nf++) {
            int gc = nbase + warp_n * 64 + nf * 8 + (lane & 3) * 2;
            float2 bb = *reinterpret_cast<const float2*>(&bias[gc]);
            int r0 = bm + warp_m * (16 * MF) + mf * 16 + (lane >> 2);
#pragma unroll
            for (int hh = 0; hh < 2; hh++) {
                int gr = r0 + hh * 8;
                if (gr >= M) continue;
                float vx = acc[mf][nf][hh * 2 + 0] + bb.x;
                float vy = acc[mf][nf][hh * 2 + 1] + bb.y;
                if (HOUT) {
                    __half hx, hy, lx, ly;
                    split2(vx, hx, lx); split2(vy, hy, ly);
                    *reinterpret_cast<uint32_t*>(&OutHi[(size_t)gr * D + gc]) =
                        packh(hx, hy);
                    *reinterpret_cast<uint32_t*>(&OutLo[(size_t)gr * D + gc]) =
                        packh(lx, ly);
                } else {
                    if (resid) {
                        float2 rr = *reinterpret_cast<const float2*>(
                            &resid[(size_t)gr * D + gc]);
                        vx += rr.x; vy += rr.y;
                    }
                    float2 v; v.x = vx; v.y = vy;
                    *reinterpret_cast<float2*>(&o0[(size_t)gr * D + gc]) = v;
                }
            }
        }
    }
}

// ---------------------------------------------------------------------------
// starts
// ---------------------------------------------------------------------------
__global__ void starts_kernel(const int* __restrict__ batch, int N) {
    int i = blockIdx.x * blockDim.x + threadIdx.x;
    if (i >= N) return;
    int b = batch[i];
    if (i == 0 || batch[i - 1] != b) g_starts[b] = i;
    if (i == N - 1) g_starts[NB] = N;
}

// ---------------------------------------------------------------------------
// mma attention (R8-proven): one block per (b,h), 8 warps.
// ---------------------------------------------------------------------------
#define AT_PHI   0
#define AT_PLO   32768
#define AT_Q     0
#define AT_K     16384
#define AT_VTHI  65536
#define AT_VTLO  73728
#define AT_PMAX  81920
#define AT_PSUM  83968
#define AT_LINV  86016
#define AT_SMEM  86528

__global__ void __launch_bounds__(256, 1)
attn_mma(const float* __restrict__ attn_bias) {
    extern __shared__ __align__(128) char sm[];
    uint32_t sb = smem_to_u32(sm);
    int tid = threadIdx.x;
    int lane = tid & 31;
    int wid = tid >> 5;
    int bh = blockIdx.x;
    int b = bh >> 4;
    int h = bh & 15;
    int s0 = g_starts[b];
    int n = g_starts[b + 1] - s0;

    {
        int row = tid >> 1;
        int part = tid & 1;
        const __half* qp = part ? g_qlo : g_qhi;
        const __half* kp = part ? g_klo : g_khi;
        size_t src = (size_t)(s0 + row) * D + h * HS;
#pragma unroll
        for (int i = 0; i < 4; i++) {
            uint4 qv = make_uint4(0, 0, 0, 0), kv = make_uint4(0, 0, 0, 0);
            if (row < n) {
                qv = *reinterpret_cast<const uint4*>(&qp[src + i * 8]);
                kv = *reinterpret_cast<const uint4*>(&kp[src + i * 8]);
            }
            uint32_t off = SWZ128((uint32_t)(row * 128 + part * 64 + i * 16));
            *reinterpret_cast<uint4*>(sm + AT_Q + off) = qv;
            *reinterpret_cast<uint4*>(sm + AT_K + off) = kv;
        }
    }
    {
        int j = tid >> 1;
        int part = tid & 1;
        size_t src = (size_t)(s0 + j) * D + h * HS + part * 16;
#pragma unroll
        for (int rep = 0; rep < 2; rep++) {
            uint4 hv = make_uint4(0, 0, 0, 0), lv = make_uint4(0, 0, 0, 0);
            if (j < n) {
                hv = *reinterpret_cast<const uint4*>(&g_vhi[src + rep * 8]);
                lv = *reinterpret_cast<const uint4*>(&g_vlo[src + rep * 8]);
            }
            const __half* hp = reinterpret_cast<const __half*>(&hv);
            const __half* lp = reinterpret_cast<const __half*>(&lv);
#pragma unroll
            for (int i = 0; i < 8; i++) {
                int d = part * 16 + rep * 8 + i;
                uint32_t off = SWZ256((uint32_t)(d * 256 + j * 2));
                *reinterpret_cast<__half*>(sm + AT_VTHI + off) = hp[i];
                *reinterpret_cast<__half*>(sm + AT_VTLO + off) = lp[i];
            }
        }
    }
    __syncthreads();

    int warp_m = wid & 1;
    int warp_n = wid >> 1;
    float sc[4][4][4];
#pragma unroll
    for (int i = 0; i < 4; i++)
#pragma unroll
        for (int j = 0; j < 4; j++)
#pragma unroll
            for (int k = 0; k < 4; k++) sc[i][j][k] = 0.f;

#pragma unroll
    for (int ks = 0; ks < 2; ks++) {
        uint32_t ah[4][4], al[4][4];
#pragma unroll
        for (int mf = 0; mf < 4; mf++) {
            int row = warp_m * 64 + mf * 16 + (lane & 15);
            uint32_t off = (uint32_t)(row * 128 + ks * 32 + ((lane >> 4) << 4));
            ldsm4(ah[mf], sb + AT_Q + SWZ128(off));
            ldsm4(al[mf], sb + AT_Q + SWZ128(off + 64));
        }
        uint32_t bh2[4][2], bl2[4][2];
#pragma unroll
        for (int np = 0; np < 2; np++) {
            int g = lane >> 3;
            int nn = warp_n * 32 + np * 16 + ((g >> 1) << 3) + (lane & 7);
            uint32_t off = (uint32_t)(nn * 128 + ks * 32 + ((g & 1) << 4));
            uint32_t r[4];
            ldsm4(r, sb + AT_K + SWZ128(off));
            bh2[np * 2][0] = r[0]; bh2[np * 2][1] = r[1];
            bh2[np * 2 + 1][0] = r[2]; bh2[np * 2 + 1][1] = r[3];
            ldsm4(r, sb + AT_K + SWZ128(off + 64));
            bl2[np * 2][0] = r[0]; bl2[np * 2][1] = r[1];
            bl2[np * 2 + 1][0] = r[2]; bl2[np * 2 + 1][1] = r[3];
        }
#pragma unroll
        for (int mf = 0; mf < 4; mf++)
#pragma unroll
            for (int nf = 0; nf < 4; nf++) {
                mma16816(sc[mf][nf], ah[mf], bh2[nf]);
                mma16816(sc[mf][nf], ah[mf], bl2[nf]);
                mma16816(sc[mf][nf], al[mf], bh2[nf]);
            }
    }

    const float* bb = attn_bias + ((size_t)(b * NHEAD + h)) * MAXN * MAXN;
#pragma unroll
    for (int mf = 0; mf < 4; mf++) {
        int r0 = warp_m * 64 + mf * 16 + (lane >> 2);
#pragma unroll
        for (int nf = 0; nf < 4; nf++) {
            int c0 = warp_n * 32 + nf * 8 + (lane & 3) * 2;
#pragma unroll
            for (int hh = 0; hh < 2; hh++) {
                int r = r0 + hh * 8;
                float2 bv = *reinterpret_cast<const float2*>(&bb[r * MAXN + c0]);
                float v0 = sc[mf][nf][hh * 2] * ATT_SCALE + bv.x;
                float v1 = sc[mf][nf][hh * 2 + 1] * ATT_SCALE + bv.y;
                if (c0 >= n) v0 = -1e30f;
                if (c0 + 1 >= n) v1 = -1e30f;
                sc[mf][nf][hh * 2] = v0;
                sc[mf][nf][hh * 2 + 1] = v1;
            }
        }
    }

#pragma unroll
    for (int mf = 0; mf < 4; mf++)
#pragma unroll
        for (int hh = 0; hh < 2; hh++) {
            float mx = -1e30f;
#pragma unroll
            for (int nf = 0; nf < 4; nf++)
                mx = fmaxf(mx, fmaxf(sc[mf][nf][hh * 2], sc[mf][nf][hh * 2 + 1]));
            mx = fmaxf(mx, __shfl_xor_sync(0xffffffffu, mx, 1));
            mx = fmaxf(mx, __shfl_xor_sync(0xffffffffu, mx, 2));
            int row = warp_m * 64 + mf * 16 + (lane >> 2) + hh * 8;
            if ((lane & 3) == 0)
                *reinterpret_cast<float*>(sm + AT_PMAX + (row * 4 + warp_n) * 4) = mx;
        }
    __syncthreads();

#pragma unroll
    for (int mf = 0; mf < 4; mf++)
#pragma unroll
        for (int hh = 0; hh < 2; hh++) {
            int row = warp_m * 64 + mf * 16 + (lane >> 2) + hh * 8;
            float4 m4 = *reinterpret_cast<float4*>(sm + AT_PMAX + row * 16);
            float m = fmaxf(fmaxf(m4.x, m4.y), fmaxf(m4.z, m4.w));
            float ssum = 0.f;
#pragma unroll
            for (int nf = 0; nf < 4; nf++) {
                float p0 = __expf(sc[mf][nf][hh * 2] - m);
                float p1 = __expf(sc[mf][nf][hh * 2 + 1] - m);
                ssum += p0 + p1;
                int c0 = warp_n * 32 + nf * 8 + (lane & 3) * 2;
                __half h0, h1, l0, l1;
                split2(p0, h0, l0); split2(p1, h1, l1);
                uint32_t off = (uint32_t)(row * 256 + c0 * 2);
                *reinterpret_cast<uint32_t*>(sm + AT_PHI + SWZ256(off)) = packh(h0, h1);
                *reinterpret_cast<uint32_t*>(sm + AT_PLO + SWZ256(off)) = packh(l0, l1);
            }
            ssum += __shfl_xor_sync(0xffffffffu, ssum, 1);
            ssum += __shfl_xor_sync(0xffffffffu, ssum, 2);
            if ((lane & 3) == 0)
                *reinterpret_cast<float*>(sm + AT_PSUM + (row * 4 + warp_n) * 4) = ssum;
        }
    __syncthreads();

    if (tid < 128) {
        float4 s4 = *reinterpret_cast<float4*>(sm + AT_PSUM + tid * 16);
        float l = s4.x + s4.y + s4.z + s4.w;
        *reinterpret_cast<float*>(sm + AT_LINV + tid * 4) = 1.f / l;
    }
    __syncthreads();

    float oc[4][4];
#pragma unroll
    for (int j = 0; j < 4; j++)
#pragma unroll
        for (int k = 0; k < 4; k++) oc[j][k] = 0.f;

#pragma unroll
    for (int ks = 0; ks < 8; ks++) {
        uint32_t ph[4], pl[4];
        {
            int row = wid * 16 + (lane & 15);
            uint32_t off = (uint32_t)(row * 256 + ks * 32 + ((lane >> 4) << 4));
            ldsm4(ph, sb + AT_PHI + SWZ256(off));
            ldsm4(pl, sb + AT_PLO + SWZ256(off));
        }
        uint32_t vh[4][2], vl[4][2];
#pragma unroll
        for (int np = 0; np < 2; np++) {
            int g = lane >> 3;
            int nn = np * 16 + ((g >> 1) << 3) + (lane & 7);
            uint32_t off = (uint32_t)(nn * 256 + ks * 32 + ((g & 1) << 4));
            uint32_t r[4];
            ldsm4(r, sb + AT_VTHI + SWZ256(off));
            vh[np * 2][0] = r[0]; vh[np * 2][1] = r[1];
            vh[np * 2 + 1][0] = r[2]; vh[np * 2 + 1][1] = r[3];
            ldsm4(r, sb + AT_VTLO + SWZ256(off));
            vl[np * 2][0] = r[0]; vl[np * 2][1] = r[1];
            vl[np * 2 + 1][0] = r[2]; vl[np * 2 + 1][1] = r[3];
        }
#pragma unroll
        for (int nf = 0; nf < 4; nf++) {
            mma16816(oc[nf], ph, vh[nf]);
            mma16816(oc[nf], ph, vl[nf]);
            mma16816(oc[nf], pl, vh[nf]);
        }
    }

    int r0 = wid * 16 + (lane >> 2);
#pragma unroll
    for (int hh = 0; hh < 2; hh++) {
        int row = r0 + hh * 8;
        if (row >= n) continue;
        float linv = *reinterpret_cast<float*>(sm + AT_LINV + row * 4);
        size_t base = (size_t)(s0 + row) * D + h * HS;
#pragma unroll
        for (int nf = 0; nf < 4; nf++) {
            int d0 = nf * 8 + (lane & 3) * 2;
            float o0 = oc[nf][hh * 2] * linv;
            float o1 = oc[nf][hh * 2 + 1] * linv;
            __half h0, h1, l0, l1;
            split2(o0, h0, l0); split2(o1, h1, l1);
            *reinterpret_cast<uint32_t*>(&g_ahi[base + d0]) = packh(h0, h1);
            *reinterpret_cast<uint32_t*>(&g_alo[base + d0]) = packh(l0, l1);
        }
    }
}

// ---------------------------------------------------------------------------
// LayerNorm
// ---------------------------------------------------------------------------
__global__ void __launch_bounds__(256)
ln_kernel(const float* __restrict__ ln_w, const float* __restrict__ ln_b,
          float* __restrict__ out) {
    int row = blockIdx.x;
    const float* y = g_y + (size_t)row * D;
    int tid = threadIdx.x;

    float v0 = y[tid];
    float v1 = y[tid + 256];
    float s = v0 + v1;
    float q = v0 * v0 + v1 * v1;
#pragma unroll
    for (int off = 16; off; off >>= 1) {
        s += __shfl_down_sync(0xffffffffu, s, off);
        q += __shfl_down_sync(0xffffffffu, q, off);
    }
    __shared__ float rs[8], rq[8];
    __shared__ float s_mu, s_rstd;
    if ((tid & 31) == 0) { rs[tid >> 5] = s; rq[tid >> 5] = q; }
    __syncthreads();
    if (tid == 0) {
        float S = 0.f, Q = 0.f;
#pragma unroll
        for (int i = 0; i < 8; i++) { S += rs[i]; Q += rq[i]; }
        float mu = S * (1.f / D);
        float var = Q * (1.f / D) - mu * mu;
        s_mu = mu;
        s_rstd = rsqrtf(var + LN_EPS);
    }
    __syncthreads();
    float mu = s_mu, r = s_rstd;
    out[(size_t)row * D + tid] = (v0 - mu) * r * ln_w[tid] + ln_b[tid];
    out[(size_t)row * D + tid + 256] =
        (v1 - mu) * r * ln_w[tid + 256] + ln_b[tid + 256];
}

// ---------------------------------------------------------------------------
extern "C" void kernel_launch(void* const* d_in, const int* in_sizes, int n_in,
                              void* d_out, int out_size) {
    const float* x         = (const float*)d_in[0];
    const float* attn_bias = (const float*)d_in[1];
    const float* Wq = (const float*)d_in[2];
    const float* bq = (const float*)d_in[3];
    const float* Wk = (const float*)d_in[4];
    const float* bk = (const float*)d_in[5];
    const float* Wv = (const float*)d_in[6];
    const float* bv = (const float*)d_in[7];
    const float* Wp = (const float*)d_in[8];
    const float* bp = (const float*)d_in[9];
    const float* ln_w = (const float*)d_in[10];
    const float* ln_b = (const float*)d_in[11];
    const int*   batch = (const int*)d_in[12];

    int N = in_sizes[12];
    float* out = (float*)d_out;

    float *yp;
    __half *whi, *wlo, *ahi, *alo, *qhi, *qlo, *khi, *klo, *vhi, *vlo;
    cudaGetSymbolAddress((void**)&yp, g_y);
    cudaGetSymbolAddress((void**)&whi, g_whi);
    cudaGetSymbolAddress((void**)&wlo, g_wlo);
    cudaGetSymbolAddress((void**)&ahi, g_ahi);
    cudaGetSymbolAddress((void**)&alo, g_alo);
    cudaGetSymbolAddress((void**)&qhi, g_qhi);
    cudaGetSymbolAddress((void**)&qlo, g_qlo);
    cudaGetSymbolAddress((void**)&khi, g_khi);
    cudaGetSymbolAddress((void**)&klo, g_klo);
    cudaGetSymbolAddress((void**)&vhi, g_vhi);
    cudaGetSymbolAddress((void**)&vlo, g_vlo);

    const int smem_qkv = 3 * (128 * 128 + 256 * 128);   // 147456
    const int smem_prj = 3 * (64 * 128 + 256 * 128);    // 122880
    cudaFuncSetAttribute(mma_gemm<128, 1>,
                         cudaFuncAttributeMaxDynamicSharedMemorySize, smem_qkv);
    cudaFuncSetAttribute(mma_gemm<64, 0>,
                         cudaFuncAttributeMaxDynamicSharedMemorySize, smem_prj);
    cudaFuncSetAttribute(attn_mma,
                         cudaFuncAttributeMaxDynamicSharedMemorySize, AT_SMEM);

    starts_kernel<<<(N + 255) / 256, 256>>>(batch, N);
    split_w_kernel<<<(4 * WELEM / 4 + 255) / 256, 256>>>(Wq, Wk, Wv, Wp);

    int n4 = N * D / 4;
    split_rows_kernel<<<(n4 + 255) / 256, 256>>>(x, n4);

    // Fused QKV: grid.y 0-1 -> Wq, 2-3 -> Wk, 4-5 -> Wv
    mma_gemm<128, 1><<<dim3((N + 127) / 128, 6), 512, smem_qkv>>>(
        ahi, alo, whi, wlo, WELEM, bq, bk, bv, nullptr,
        qhi, qlo, khi, klo, vhi, vlo, nullptr, N);

    attn_mma<<<NB * NHEAD, 256, AT_SMEM>>>(attn_bias);

    // Output projection + bias + residual (W plane 3)
    mma_gemm<64, 0><<<dim3((N + 63) / 64, 2), 512, smem_prj>>>(
        ahi, alo, whi + 3 * WELEM, wlo + 3 * WELEM, 0,
        bp, bp, bp, yp,
        nullptr, nullptr, nullptr, nullptr, nullptr, nullptr, x, N);

    ln_kernel<<<N, 256>>>(ln_w, ln_b, out);
}

// round 12
// speedup vs baseline: 1.1308x; 1.1308x over previous
#include <cuda_runtime.h>
#include <cuda_fp16.h>
#include <math.h>
#include <stdint.h>

// Problem constants
#define D     512
#define NHEAD 16
#define HS    32
#define NB    64
#define MAXN  128
#define ATT_SCALE 0.17677669529663687f
#define LN_EPS 1e-5f
#define MAX_ROWS 8192
#define WELEM (512 * 512)

// Scratch
__device__ float g_y[MAX_ROWS * D];
__device__ int   g_starts[NB + 1];
__device__ __half g_whi[4 * WELEM];
__device__ __half g_wlo[4 * WELEM];
__device__ __half g_ahi[MAX_ROWS * D];
__device__ __half g_alo[MAX_ROWS * D];
__device__ __half g_qhi[MAX_ROWS * D];
__device__ __half g_qlo[MAX_ROWS * D];
__device__ __half g_khi[MAX_ROWS * D];
__device__ __half g_klo[MAX_ROWS * D];
__device__ __half g_vhi[MAX_ROWS * D];
__device__ __half g_vlo[MAX_ROWS * D];

#define SWZ128(o) ((o) ^ (((o) >> 3) & 0x70u))
#define SWZ256(o) ((o) ^ (((o) >> 4) & 0x70u))

__device__ __forceinline__ uint32_t smem_to_u32(const void* p) {
    uint32_t a;
    asm("{ .reg .u64 t; cvta.to.shared.u64 t, %1; cvt.u32.u64 %0, t; }"
        : "=r"(a) : "l"(p));
    return a;
}
__device__ __forceinline__ void ldsm4(uint32_t* r, uint32_t addr) {
    asm volatile("ldmatrix.sync.aligned.m8n8.x4.shared.b16 {%0,%1,%2,%3}, [%4];"
                 : "=r"(r[0]), "=r"(r[1]), "=r"(r[2]), "=r"(r[3]) : "r"(addr));
}
// non-volatile: register-only op, ptxas may schedule freely
__device__ __forceinline__ void mma16816(float* c, const uint32_t* a,
                                         const uint32_t* b) {
    asm("mma.sync.aligned.m16n8k16.row.col.f32.f16.f16.f32 "
        "{%0,%1,%2,%3}, {%4,%5,%6,%7}, {%8,%9}, {%0,%1,%2,%3};"
        : "+f"(c[0]), "+f"(c[1]), "+f"(c[2]), "+f"(c[3])
        : "r"(a[0]), "r"(a[1]), "r"(a[2]), "r"(a[3]), "r"(b[0]), "r"(b[1]));
}
__device__ __forceinline__ uint32_t packh(__half a, __half b) {
    __half2 h = __halves2half2(a, b);
    return *reinterpret_cast<uint32_t*>(&h);
}
__device__ __forceinline__ void split2(float x, __half& hi, __half& lo) {
    hi = __float2half_rn(x);
    lo = __float2half_rn(x - __half2float(hi));
}
__device__ __forceinline__ void cp_async16(uint32_t dst, const void* src, int sz) {
    asm volatile("cp.async.cg.shared.global [%0], [%1], 16, %2;"
                 :: "r"(dst), "l"(src), "r"(sz) : "memory");
}
#define CP_COMMIT() asm volatile("cp.async.commit_group;" ::: "memory")
#define CP_WAIT(n)  asm volatile("cp.async.wait_group %0;" :: "n"(n) : "memory")

// ---------------------------------------------------------------------------
// split kernels
// ---------------------------------------------------------------------------
__global__ void split_w_kernel(const float* __restrict__ Wq,
                               const float* __restrict__ Wk,
                               const float* __restrict__ Wv,
                               const float* __restrict__ Wp) {
    int i = blockIdx.x * blockDim.x + threadIdx.x;
    int i4 = i * 4;
    if (i4 >= 4 * WELEM) return;
    int w = i4 >> 18;
    int off = i4 & (WELEM - 1);
    const float* src = (w == 0) ? Wq : (w == 1) ? Wk : (w == 2) ? Wv : Wp;
    float4 v = *reinterpret_cast<const float4*>(&src[off]);
    __half hx, hy, hz, hw, lx, ly, lz, lw;
    split2(v.x, hx, lx); split2(v.y, hy, ly);
    split2(v.z, hz, lz); split2(v.w, hw, lw);
    uint2 hi, lo;
    hi.x = packh(hx, hy); hi.y = packh(hz, hw);
    lo.x = packh(lx, ly); lo.y = packh(lz, lw);
    reinterpret_cast<uint2*>(g_whi)[i] = hi;
    reinterpret_cast<uint2*>(g_wlo)[i] = lo;
}

__global__ void split_rows_kernel(const float* __restrict__ src, int n4) {
    int i = blockIdx.x * blockDim.x + threadIdx.x;
    if (i >= n4) return;
    float4 v = reinterpret_cast<const float4*>(src)[i];
    __half hx, hy, hz, hw, lx, ly, lz, lw;
    split2(v.x, hx, lx); split2(v.y, hy, ly);
    split2(v.z, hz, lz); split2(v.w, hw, lw);
    uint2 hi, lo;
    hi.x = packh(hx, hy); hi.y = packh(hz, hw);
    lo.x = packh(lx, ly); lo.y = packh(lz, lw);
    reinterpret_cast<uint2*>(g_ahi)[i] = hi;
    reinterpret_cast<uint2*>(g_alo)[i] = lo;
}

// ---------------------------------------------------------------------------
// split-fp16 (3-term) mma.sync GEMM.
// Block tile BM x 128, 256 thr = 8 warps (4m x 2n), warp tile (BM/4) x 64.
// 2 CTAs/SM co-resident: barrier stalls in one CTA are covered by the other.
// cp.async staging, 3-stage circular buffer.
// grid.y ntile: wsel = ntile>>2 (weight plane), nbase = (ntile&3)*128.
// ---------------------------------------------------------------------------
#define GBK 32
#define NSTAGE (D / GBK)

template <int BM, int HOUT>
__global__ void __launch_bounds__(256, 2)
mma_gemm(const __half* __restrict__ Ahi, const __half* __restrict__ Alo,
         const __half* __restrict__ Whi, const __half* __restrict__ Wlo,
         int wstride,
         const float* __restrict__ b0, const float* __restrict__ b1,
         const float* __restrict__ b2,
         float* __restrict__ o0,
         __half* __restrict__ oh0, __half* __restrict__ ol0,
         __half* __restrict__ oh1, __half* __restrict__ ol1,
         __half* __restrict__ oh2, __half* __restrict__ ol2,
         const float* __restrict__ resid, int M) {
    constexpr int MF = BM / 64;              // 2 for BM=128, 1 for BM=64
    constexpr int ABYTES = BM * 128;
    constexpr int BBYTES = 128 * 128;
    constexpr int BUF = ABYTES + BBYTES;
    constexpr int A_ITER = (ABYTES / 16) / 256;
    constexpr int B_ITER = (BBYTES / 16) / 256;
    extern __shared__ __align__(128) char smem[];
    uint32_t sbase = smem_to_u32(smem);
    int tid = threadIdx.x;
    int lane = tid & 31;
    int wid = tid >> 5;
    int warp_m = wid & 3;                    // 4 m-warps
    int warp_n = wid >> 2;                   // 2 n-warps
    int bm = blockIdx.x * BM;
    int ntile = blockIdx.y;
    int wsel = ntile >> 2;
    const __half* WH = Whi + (size_t)wsel * wstride;
    const __half* WL = Wlo + (size_t)wsel * wstride;
    const float* bias = (wsel == 0) ? b0 : (wsel == 1 ? b1 : b2);
    __half* OutHi = (wsel == 0) ? oh0 : (wsel == 1 ? oh1 : oh2);
    __half* OutLo = (wsel == 0) ? ol0 : (wsel == 1 ? ol1 : ol2);
    int nbase = (ntile & 3) * 128;

    auto stage = [&](int s, int d) {
        int k0 = s * GBK;
        uint32_t base = sbase + d * BUF;
#pragma unroll
        for (int j = 0; j < A_ITER; j++) {
            int c = tid + j * 256;
            int row = c >> 3, sub = c & 7, plane = sub >> 2, i = sub & 3;
            uint32_t dst = base + SWZ128((uint32_t)(row * 128 + plane * 64 + i * 16));
            const __half* sp = plane ? Alo : Ahi;
            int gr = bm + row;
            const __half* src = sp + (size_t)gr * D + k0 + i * 8;
            cp_async16(dst, src, gr < M ? 16 : 0);
        }
#pragma unroll
        for (int j = 0; j < B_ITER; j++) {
            int c = tid + j * 256;
            int row = c >> 3, sub = c & 7, plane = sub >> 2, i = sub & 3;
            uint32_t dst = base + ABYTES +
                           SWZ128((uint32_t)(row * 128 + plane * 64 + i * 16));
            const __half* sp = plane ? WL : WH;
            const __half* src = sp + (size_t)(nbase + row) * D + k0 + i * 8;
            cp_async16(dst, src, 16);
        }
        CP_COMMIT();
    };

    float acc[MF][8][4];
#pragma unroll
    for (int i = 0; i < MF; i++)
#pragma unroll
        for (int j = 0; j < 8; j++)
#pragma unroll
            for (int k = 0; k < 4; k++) acc[i][j][k] = 0.f;

    stage(0, 0);
    stage(1, 1);

    for (int s = 0; s < NSTAGE; s++) {
        if (s == NSTAGE - 1) CP_WAIT(0); else CP_WAIT(1);
        __syncthreads();
        if (s + 2 < NSTAGE) stage(s + 2, (s + 2) % 3);

        uint32_t Abase = sbase + (s % 3) * BUF;
        uint32_t Bbase = Abase + ABYTES;
#pragma unroll
        for (int ks = 0; ks < 2; ks++) {
            uint32_t ah[MF][4], al[MF][4];
#pragma unroll
            for (int mf = 0; mf < MF; mf++) {
                int row = warp_m * (16 * MF) + mf * 16 + (lane & 15);
                uint32_t off =
                    (uint32_t)(row * 128 + ks * 32 + ((lane >> 4) << 4));
                ldsm4(ah[mf], Abase + SWZ128(off));
                ldsm4(al[mf], Abase + SWZ128(off + 64));
            }
#pragma unroll
            for (int np = 0; np < 4; np++) {
                int g = lane >> 3;
                int n = warp_n * 64 + np * 16 + ((g >> 1) << 3) + (lane & 7);
                uint32_t off = (uint32_t)(n * 128 + ks * 32 + ((g & 1) << 4));
                uint32_t rh[4], rl[4];
                ldsm4(rh, Bbase + SWZ128(off));
                ldsm4(rl, Bbase + SWZ128(off + 64));
#pragma unroll
                for (int mf = 0; mf < MF; mf++) {
                    mma16816(acc[mf][np * 2], ah[mf], rh);
                    mma16816(acc[mf][np * 2 + 1], ah[mf], rh + 2);
                    mma16816(acc[mf][np * 2], ah[mf], rl);
                    mma16816(acc[mf][np * 2 + 1], ah[mf], rl + 2);
                    mma16816(acc[mf][np * 2], al[mf], rh);
                    mma16816(acc[mf][np * 2 + 1], al[mf], rh + 2);
                }
            }
        }
    }

    // ---- epilogue
#pragma unroll
    for (int mf = 0; mf < MF; mf++) {
#pragma unroll
        for (int nf = 0; nf < 8; nf++) {
            int gc = nbase + warp_n * 64 + nf * 8 + (lane & 3) * 2;
            float2 bb = *reinterpret_cast<const float2*>(&bias[gc]);
            int r0 = bm + warp_m * (16 * MF) + mf * 16 + (lane >> 2);
#pragma unroll
            for (int hh = 0; hh < 2; hh++) {
                int gr = r0 + hh * 8;
                if (gr >= M) continue;
                float vx = acc[mf][nf][hh * 2 + 0] + bb.x;
                float vy = acc[mf][nf][hh * 2 + 1] + bb.y;
                if (HOUT) {
                    __half hx, hy, lx, ly;
                    split2(vx, hx, lx); split2(vy, hy, ly);
                    *reinterpret_cast<uint32_t*>(&OutHi[(size_t)gr * D + gc]) =
                        packh(hx, hy);
                    *reinterpret_cast<uint32_t*>(&OutLo[(size_t)gr * D + gc]) =
                        packh(lx, ly);
                } else {
                    if (resid) {
                        float2 rr = *reinterpret_cast<const float2*>(
                            &resid[(size_t)gr * D + gc]);
                        vx += rr.x; vy += rr.y;
                    }
                    float2 v; v.x = vx; v.y = vy;
                    *reinterpret_cast<float2*>(&o0[(size_t)gr * D + gc]) = v;
                }
            }
        }
    }
}

// ---------------------------------------------------------------------------
// starts
// ---------------------------------------------------------------------------
__global__ void starts_kernel(const int* __restrict__ batch, int N) {
    int i = blockIdx.x * blockDim.x + threadIdx.x;
    if (i >= N) return;
    int b = batch[i];
    if (i == 0 || batch[i - 1] != b) g_starts[b] = i;
    if (i == N - 1) g_starts[NB] = N;
}

// ---------------------------------------------------------------------------
// mma attention (R8-proven): one block per (b,h), 8 warps.
// ---------------------------------------------------------------------------
#define AT_PHI   0
#define AT_PLO   32768
#define AT_Q     0
#define AT_K     16384
#define AT_VTHI  65536
#define AT_VTLO  73728
#define AT_PMAX  81920
#define AT_PSUM  83968
#define AT_LINV  86016
#define AT_SMEM  86528

__global__ void __launch_bounds__(256, 1)
attn_mma(const float* __restrict__ attn_bias) {
    extern __shared__ __align__(128) char sm[];
    uint32_t sb = smem_to_u32(sm);
    int tid = threadIdx.x;
    int lane = tid & 31;
    int wid = tid >> 5;
    int bh = blockIdx.x;
    int b = bh >> 4;
    int h = bh & 15;
    int s0 = g_starts[b];
    int n = g_starts[b + 1] - s0;

    {
        int row = tid >> 1;
        int part = tid & 1;
        const __half* qp = part ? g_qlo : g_qhi;
        const __half* kp = part ? g_klo : g_khi;
        size_t src = (size_t)(s0 + row) * D + h * HS;
#pragma unroll
        for (int i = 0; i < 4; i++) {
            uint4 qv = make_uint4(0, 0, 0, 0), kv = make_uint4(0, 0, 0, 0);
            if (row < n) {
                qv = *reinterpret_cast<const uint4*>(&qp[src + i * 8]);
                kv = *reinterpret_cast<const uint4*>(&kp[src + i * 8]);
            }
            uint32_t off = SWZ128((uint32_t)(row * 128 + part * 64 + i * 16));
            *reinterpret_cast<uint4*>(sm + AT_Q + off) = qv;
            *reinterpret_cast<uint4*>(sm + AT_K + off) = kv;
        }
    }
    {
        int j = tid >> 1;
        int part = tid & 1;
        size_t src = (size_t)(s0 + j) * D + h * HS + part * 16;
#pragma unroll
        for (int rep = 0; rep < 2; rep++) {
            uint4 hv = make_uint4(0, 0, 0, 0), lv = make_uint4(0, 0, 0, 0);
            if (j < n) {
                hv = *reinterpret_cast<const uint4*>(&g_vhi[src + rep * 8]);
                lv = *reinterpret_cast<const uint4*>(&g_vlo[src + rep * 8]);
            }
            const __half* hp = reinterpret_cast<const __half*>(&hv);
            const __half* lp = reinterpret_cast<const __half*>(&lv);
#pragma unroll
            for (int i = 0; i < 8; i++) {
                int d = part * 16 + rep * 8 + i;
                uint32_t off = SWZ256((uint32_t)(d * 256 + j * 2));
                *reinterpret_cast<__half*>(sm + AT_VTHI + off) = hp[i];
                *reinterpret_cast<__half*>(sm + AT_VTLO + off) = lp[i];
            }
        }
    }
    __syncthreads();

    int warp_m = wid & 1;
    int warp_n = wid >> 1;
    float sc[4][4][4];
#pragma unroll
    for (int i = 0; i < 4; i++)
#pragma unroll
        for (int j = 0; j < 4; j++)
#pragma unroll
            for (int k = 0; k < 4; k++) sc[i][j][k] = 0.f;

#pragma unroll
    for (int ks = 0; ks < 2; ks++) {
        uint32_t ah[4][4], al[4][4];
#pragma unroll
        for (int mf = 0; mf < 4; mf++) {
            int row = warp_m * 64 + mf * 16 + (lane & 15);
            uint32_t off = (uint32_t)(row * 128 + ks * 32 + ((lane >> 4) << 4));
            ldsm4(ah[mf], sb + AT_Q + SWZ128(off));
            ldsm4(al[mf], sb + AT_Q + SWZ128(off + 64));
        }
        uint32_t bh2[4][2], bl2[4][2];
#pragma unroll
        for (int np = 0; np < 2; np++) {
            int g = lane >> 3;
            int nn = warp_n * 32 + np * 16 + ((g >> 1) << 3) + (lane & 7);
            uint32_t off = (uint32_t)(nn * 128 + ks * 32 + ((g & 1) << 4));
            uint32_t r[4];
            ldsm4(r, sb + AT_K + SWZ128(off));
            bh2[np * 2][0] = r[0]; bh2[np * 2][1] = r[1];
            bh2[np * 2 + 1][0] = r[2]; bh2[np * 2 + 1][1] = r[3];
            ldsm4(r, sb + AT_K + SWZ128(off + 64));
            bl2[np * 2][0] = r[0]; bl2[np * 2][1] = r[1];
            bl2[np * 2 + 1][0] = r[2]; bl2[np * 2 + 1][1] = r[3];
        }
#pragma unroll
        for (int mf = 0; mf < 4; mf++)
#pragma unroll
            for (int nf = 0; nf < 4; nf++) {
                mma16816(sc[mf][nf], ah[mf], bh2[nf]);
                mma16816(sc[mf][nf], ah[mf], bl2[nf]);
                mma16816(sc[mf][nf], al[mf], bh2[nf]);
            }
    }

    const float* bb = attn_bias + ((size_t)(b * NHEAD + h)) * MAXN * MAXN;
#pragma unroll
    for (int mf = 0; mf < 4; mf++) {
        int r0 = warp_m * 64 + mf * 16 + (lane >> 2);
#pragma unroll
        for (int nf = 0; nf < 4; nf++) {
            int c0 = warp_n * 32 + nf * 8 + (lane & 3) * 2;
#pragma unroll
            for (int hh = 0; hh < 2; hh++) {
                int r = r0 + hh * 8;
                float2 bv = *reinterpret_cast<const float2*>(&bb[r * MAXN + c0]);
                float v0 = sc[mf][nf][hh * 2] * ATT_SCALE + bv.x;
                float v1 = sc[mf][nf][hh * 2 + 1] * ATT_SCALE + bv.y;
                if (c0 >= n) v0 = -1e30f;
                if (c0 + 1 >= n) v1 = -1e30f;
                sc[mf][nf][hh * 2] = v0;
                sc[mf][nf][hh * 2 + 1] = v1;
            }
        }
    }

#pragma unroll
    for (int mf = 0; mf < 4; mf++)
#pragma unroll
        for (int hh = 0; hh < 2; hh++) {
            float mx = -1e30f;
#pragma unroll
            for (int nf = 0; nf < 4; nf++)
                mx = fmaxf(mx, fmaxf(sc[mf][nf][hh * 2], sc[mf][nf][hh * 2 + 1]));
            mx = fmaxf(mx, __shfl_xor_sync(0xffffffffu, mx, 1));
            mx = fmaxf(mx, __shfl_xor_sync(0xffffffffu, mx, 2));
            int row = warp_m * 64 + mf * 16 + (lane >> 2) + hh * 8;
            if ((lane & 3) == 0)
                *reinterpret_cast<float*>(sm + AT_PMAX + (row * 4 + warp_n) * 4) = mx;
        }
    __syncthreads();

#pragma unroll
    for (int mf = 0; mf < 4; mf++)
#pragma unroll
        for (int hh = 0; hh < 2; hh++) {
            int row = warp_m * 64 + mf * 16 + (lane >> 2) + hh * 8;
            float4 m4 = *reinterpret_cast<float4*>(sm + AT_PMAX + row * 16);
            float m = fmaxf(fmaxf(m4.x, m4.y), fmaxf(m4.z, m4.w));
            float ssum = 0.f;
#pragma unroll
            for (int nf = 0; nf < 4; nf++) {
                float p0 = __expf(sc[mf][nf][hh * 2] - m);
                float p1 = __expf(sc[mf][nf][hh * 2 + 1] - m);
                ssum += p0 + p1;
                int c0 = warp_n * 32 + nf * 8 + (lane & 3) * 2;
                __half h0, h1, l0, l1;
                split2(p0, h0, l0); split2(p1, h1, l1);
                uint32_t off = (uint32_t)(row * 256 + c0 * 2);
                *reinterpret_cast<uint32_t*>(sm + AT_PHI + SWZ256(off)) = packh(h0, h1);
                *reinterpret_cast<uint32_t*>(sm + AT_PLO + SWZ256(off)) = packh(l0, l1);
            }
            ssum += __shfl_xor_sync(0xffffffffu, ssum, 1);
            ssum += __shfl_xor_sync(0xffffffffu, ssum, 2);
            if ((lane & 3) == 0)
                *reinterpret_cast<float*>(sm + AT_PSUM + (row * 4 + warp_n) * 4) = ssum;
        }
    __syncthreads();

    if (tid < 128) {
        float4 s4 = *reinterpret_cast<float4*>(sm + AT_PSUM + tid * 16);
        float l = s4.x + s4.y + s4.z + s4.w;
        *reinterpret_cast<float*>(sm + AT_LINV + tid * 4) = 1.f / l;
    }
    __syncthreads();

    float oc[4][4];
#pragma unroll
    for (int j = 0; j < 4; j++)
#pragma unroll
        for (int k = 0; k < 4; k++) oc[j][k] = 0.f;

#pragma unroll
    for (int ks = 0; ks < 8; ks++) {
        uint32_t ph[4], pl[4];
        {
            int row = wid * 16 + (lane & 15);
            uint32_t off = (uint32_t)(row * 256 + ks * 32 + ((lane >> 4) << 4));
            ldsm4(ph, sb + AT_PHI + SWZ256(off));
            ldsm4(pl, sb + AT_PLO + SWZ256(off));
        }
        uint32_t vh[4][2], vl[4][2];
#pragma unroll
        for (int np = 0; np < 2; np++) {
            int g = lane >> 3;
            int nn = np * 16 + ((g >> 1) << 3) + (lane & 7);
            uint32_t off = (uint32_t)(nn * 256 + ks * 32 + ((g & 1) << 4));
            uint32_t r[4];
            ldsm4(r, sb + AT_VTHI + SWZ256(off));
            vh[np * 2][0] = r[0]; vh[np * 2][1] = r[1];
            vh[np * 2 + 1][0] = r[2]; vh[np * 2 + 1][1] = r[3];
            ldsm4(r, sb + AT_VTLO + SWZ256(off));
            vl[np * 2][0] = r[0]; vl[np * 2][1] = r[1];
            vl[np * 2 + 1][0] = r[2]; vl[np * 2 + 1][1] = r[3];
        }
#pragma unroll
        for (int nf = 0; nf < 4; nf++) {
            mma16816(oc[nf], ph, vh[nf]);
            mma16816(oc[nf], ph, vl[nf]);
            mma16816(oc[nf], pl, vh[nf]);
        }
    }

    int r0 = wid * 16 + (lane >> 2);
#pragma unroll
    for (int hh = 0; hh < 2; hh++) {
        int row = r0 + hh * 8;
        if (row >= n) continue;
        float linv = *reinterpret_cast<float*>(sm + AT_LINV + row * 4);
        size_t base = (size_t)(s0 + row) * D + h * HS;
#pragma unroll
        for (int nf = 0; nf < 4; nf++) {
            int d0 = nf * 8 + (lane & 3) * 2;
            float o0 = oc[nf][hh * 2] * linv;
            float o1 = oc[nf][hh * 2 + 1] * linv;
            __half h0, h1, l0, l1;
            split2(o0, h0, l0); split2(o1, h1, l1);
            *reinterpret_cast<uint32_t*>(&g_ahi[base + d0]) = packh(h0, h1);
            *reinterpret_cast<uint32_t*>(&g_alo[base + d0]) = packh(l0, l1);
        }
    }
}

// ---------------------------------------------------------------------------
// LayerNorm
// ---------------------------------------------------------------------------
__global__ void __launch_bounds__(256)
ln_kernel(const float* __restrict__ ln_w, const float* __restrict__ ln_b,
          float* __restrict__ out) {
    int row = blockIdx.x;
    const float* y = g_y + (size_t)row * D;
    int tid = threadIdx.x;

    float v0 = y[tid];
    float v1 = y[tid + 256];
    float s = v0 + v1;
    float q = v0 * v0 + v1 * v1;
#pragma unroll
    for (int off = 16; off; off >>= 1) {
        s += __shfl_down_sync(0xffffffffu, s, off);
        q += __shfl_down_sync(0xffffffffu, q, off);
    }
    __shared__ float rs[8], rq[8];
    __shared__ float s_mu, s_rstd;
    if ((tid & 31) == 0) { rs[tid >> 5] = s; rq[tid >> 5] = q; }
    __syncthreads();
    if (tid == 0) {
        float S = 0.f, Q = 0.f;
#pragma unroll
        for (int i = 0; i < 8; i++) { S += rs[i]; Q += rq[i]; }
        float mu = S * (1.f / D);
        float var = Q * (1.f / D) - mu * mu;
        s_mu = mu;
        s_rstd = rsqrtf(var + LN_EPS);
    }
    __syncthreads();
    float mu = s_mu, r = s_rstd;
    out[(size_t)row * D + tid] = (v0 - mu) * r * ln_w[tid] + ln_b[tid];
    out[(size_t)row * D + tid + 256] =
        (v1 - mu) * r * ln_w[tid + 256] + ln_b[tid + 256];
}

// ---------------------------------------------------------------------------
extern "C" void kernel_launch(void* const* d_in, const int* in_sizes, int n_in,
                              void* d_out, int out_size) {
    const float* x         = (const float*)d_in[0];
    const float* attn_bias = (const float*)d_in[1];
    const float* Wq = (const float*)d_in[2];
    const float* bq = (const float*)d_in[3];
    const float* Wk = (const float*)d_in[4];
    const float* bk = (const float*)d_in[5];
    const float* Wv = (const float*)d_in[6];
    const float* bv = (const float*)d_in[7];
    const float* Wp = (const float*)d_in[8];
    const float* bp = (const float*)d_in[9];
    const float* ln_w = (const float*)d_in[10];
    const float* ln_b = (const float*)d_in[11];
    const int*   batch = (const int*)d_in[12];

    int N = in_sizes[12];
    float* out = (float*)d_out;

    float *yp;
    __half *whi, *wlo, *ahi, *alo, *qhi, *qlo, *khi, *klo, *vhi, *vlo;
    cudaGetSymbolAddress((void**)&yp, g_y);
    cudaGetSymbolAddress((void**)&whi, g_whi);
    cudaGetSymbolAddress((void**)&wlo, g_wlo);
    cudaGetSymbolAddress((void**)&ahi, g_ahi);
    cudaGetSymbolAddress((void**)&alo, g_alo);
    cudaGetSymbolAddress((void**)&qhi, g_qhi);
    cudaGetSymbolAddress((void**)&qlo, g_qlo);
    cudaGetSymbolAddress((void**)&khi, g_khi);
    cudaGetSymbolAddress((void**)&klo, g_klo);
    cudaGetSymbolAddress((void**)&vhi, g_vhi);
    cudaGetSymbolAddress((void**)&vlo, g_vlo);

    const int smem_qkv = 3 * (128 * 128 + 128 * 128);   // 98304
    const int smem_prj = 3 * (64 * 128 + 128 * 128);    // 73728
    cudaFuncSetAttribute(mma_gemm<128, 1>,
                         cudaFuncAttributeMaxDynamicSharedMemorySize, smem_qkv);
    cudaFuncSetAttribute(mma_gemm<64, 0>,
                         cudaFuncAttributeMaxDynamicSharedMemorySize, smem_prj);
    cudaFuncSetAttribute(attn_mma,
                         cudaFuncAttributeMaxDynamicSharedMemorySize, AT_SMEM);

    starts_kernel<<<(N + 255) / 256, 256>>>(batch, N);
    split_w_kernel<<<(4 * WELEM / 4 + 255) / 256, 256>>>(Wq, Wk, Wv, Wp);

    int n4 = N * D / 4;
    split_rows_kernel<<<(n4 + 255) / 256, 256>>>(x, n4);

    // Fused QKV: grid.y 0-3 -> Wq, 4-7 -> Wk, 8-11 -> Wv (ntile&3 -> nbase)
    mma_gemm<128, 1><<<dim3((N + 127) / 128, 12), 256, smem_qkv>>>(
        ahi, alo, whi, wlo, WELEM, bq, bk, bv, nullptr,
        qhi, qlo, khi, klo, vhi, vlo, nullptr, N);

    attn_mma<<<NB * NHEAD, 256, AT_SMEM>>>(attn_bias);

    // Output projection + bias + residual (W plane 3)
    mma_gemm<64, 0><<<dim3((N + 63) / 64, 4), 256, smem_prj>>>(
        ahi, alo, whi + 3 * WELEM, wlo + 3 * WELEM, 0,
        bp, bp, bp, yp,
        nullptr, nullptr, nullptr, nullptr, nullptr, nullptr, x, N);

    ln_kernel<<<N, 256>>>(ln_w, ln_b, out);
}

// round 13
// speedup vs baseline: 1.2112x; 1.0711x over previous
#include <cuda_runtime.h>
#include <cuda_fp16.h>
#include <math.h>
#include <stdint.h>

// Problem constants
#define D     512
#define NHEAD 16
#define HS    32
#define NB    64
#define MAXN  128
#define ATT_SCALE 0.17677669529663687f
#define LN_EPS 1e-5f
#define MAX_ROWS 8192
#define WELEM (512 * 512)

// Scratch
__device__ float g_y[MAX_ROWS * D];
__device__ int   g_starts[NB + 1];
__device__ __half g_whi[4 * WELEM];
__device__ __half g_wlo[4 * WELEM];
__device__ __half g_ahi[MAX_ROWS * D];
__device__ __half g_alo[MAX_ROWS * D];
__device__ __half g_qhi[MAX_ROWS * D];
__device__ __half g_qlo[MAX_ROWS * D];
__device__ __half g_khi[MAX_ROWS * D];
__device__ __half g_klo[MAX_ROWS * D];
__device__ __half g_vhi[MAX_ROWS * D];
__device__ __half g_vlo[MAX_ROWS * D];

#define SWZ128(o) ((o) ^ (((o) >> 3) & 0x70u))
#define SWZ256(o) ((o) ^ (((o) >> 4) & 0x70u))

__device__ __forceinline__ uint32_t smem_to_u32(const void* p) {
    uint32_t a;
    asm("{ .reg .u64 t; cvta.to.shared.u64 t, %1; cvt.u32.u64 %0, t; }"
        : "=r"(a) : "l"(p));
    return a;
}
__device__ __forceinline__ void ldsm4(uint32_t* r, uint32_t addr) {
    asm volatile("ldmatrix.sync.aligned.m8n8.x4.shared.b16 {%0,%1,%2,%3}, [%4];"
                 : "=r"(r[0]), "=r"(r[1]), "=r"(r[2]), "=r"(r[3]) : "r"(addr));
}
// non-volatile: register-only op, ptxas may schedule freely
__device__ __forceinline__ void mma16816(float* c, const uint32_t* a,
                                         const uint32_t* b) {
    asm("mma.sync.aligned.m16n8k16.row.col.f32.f16.f16.f32 "
        "{%0,%1,%2,%3}, {%4,%5,%6,%7}, {%8,%9}, {%0,%1,%2,%3};"
        : "+f"(c[0]), "+f"(c[1]), "+f"(c[2]), "+f"(c[3])
        : "r"(a[0]), "r"(a[1]), "r"(a[2]), "r"(a[3]), "r"(b[0]), "r"(b[1]));
}
__device__ __forceinline__ uint32_t packh(__half a, __half b) {
    __half2 h = __halves2half2(a, b);
    return *reinterpret_cast<uint32_t*>(&h);
}
__device__ __forceinline__ void split2(float x, __half& hi, __half& lo) {
    hi = __float2half_rn(x);
    lo = __float2half_rn(x - __half2float(hi));
}
__device__ __forceinline__ void cp_async16(uint32_t dst, const void* src, int sz) {
    asm volatile("cp.async.cg.shared.global [%0], [%1], 16, %2;"
                 :: "r"(dst), "l"(src), "r"(sz) : "memory");
}
#define CP_COMMIT() asm volatile("cp.async.commit_group;" ::: "memory")
#define CP_WAIT(n)  asm volatile("cp.async.wait_group %0;" :: "n"(n) : "memory")

// ---------------------------------------------------------------------------
// Fused prologue: starts + W split + x split, one launch.
// Index space: [0, n4)           -> split x rows
//              [n4, n4+w4)       -> split W planes
//              [n4+w4, n4+w4+N)  -> segment starts
// ---------------------------------------------------------------------------
__global__ void prep_kernel(const float* __restrict__ x,
                            const float* __restrict__ Wq,
                            const float* __restrict__ Wk,
                            const float* __restrict__ Wv,
                            const float* __restrict__ Wp,
                            const int* __restrict__ batch, int N) {
    int n4 = N * D / 4;
    const int w4 = 4 * WELEM / 4;
    int i = blockIdx.x * blockDim.x + threadIdx.x;
    if (i < n4) {
        float4 v = reinterpret_cast<const float4*>(x)[i];
        __half hx, hy, hz, hw, lx, ly, lz, lw;
        split2(v.x, hx, lx); split2(v.y, hy, ly);
        split2(v.z, hz, lz); split2(v.w, hw, lw);
        uint2 hi, lo;
        hi.x = packh(hx, hy); hi.y = packh(hz, hw);
        lo.x = packh(lx, ly); lo.y = packh(lz, lw);
        reinterpret_cast<uint2*>(g_ahi)[i] = hi;
        reinterpret_cast<uint2*>(g_alo)[i] = lo;
    } else if (i < n4 + w4) {
        int j = i - n4;
        int j4 = j * 4;
        int w = j4 >> 18;
        int off = j4 & (WELEM - 1);
        const float* src = (w == 0) ? Wq : (w == 1) ? Wk : (w == 2) ? Wv : Wp;
        float4 v = *reinterpret_cast<const float4*>(&src[off]);
        __half hx, hy, hz, hw, lx, ly, lz, lw;
        split2(v.x, hx, lx); split2(v.y, hy, ly);
        split2(v.z, hz, lz); split2(v.w, hw, lw);
        uint2 hi, lo;
        hi.x = packh(hx, hy); hi.y = packh(hz, hw);
        lo.x = packh(lx, ly); lo.y = packh(lz, lw);
        reinterpret_cast<uint2*>(g_whi)[j] = hi;
        reinterpret_cast<uint2*>(g_wlo)[j] = lo;
    } else if (i < n4 + w4 + N) {
        int j = i - n4 - w4;
        int b = batch[j];
        if (j == 0 || batch[j - 1] != b) g_starts[b] = j;
        if (j == N - 1) g_starts[NB] = N;
    }
}

// ---------------------------------------------------------------------------
// split-fp16 (3-term) mma.sync GEMM (R12-proven).
// Block tile BM x 128, 256 thr = 8 warps (4m x 2n), 2 CTAs/SM.
// ---------------------------------------------------------------------------
#define GBK 32
#define NSTAGE (D / GBK)

template <int BM, int HOUT>
__global__ void __launch_bounds__(256, 2)
mma_gemm(const __half* __restrict__ Ahi, const __half* __restrict__ Alo,
         const __half* __restrict__ Whi, const __half* __restrict__ Wlo,
         int wstride,
         const float* __restrict__ b0, const float* __restrict__ b1,
         const float* __restrict__ b2,
         float* __restrict__ o0,
         __half* __restrict__ oh0, __half* __restrict__ ol0,
         __half* __restrict__ oh1, __half* __restrict__ ol1,
         __half* __restrict__ oh2, __half* __restrict__ ol2,
         const float* __restrict__ resid, int M) {
    constexpr int MF = BM / 64;
    constexpr int ABYTES = BM * 128;
    constexpr int BBYTES = 128 * 128;
    constexpr int BUF = ABYTES + BBYTES;
    constexpr int A_ITER = (ABYTES / 16) / 256;
    constexpr int B_ITER = (BBYTES / 16) / 256;
    extern __shared__ __align__(128) char smem[];
    uint32_t sbase = smem_to_u32(smem);
    int tid = threadIdx.x;
    int lane = tid & 31;
    int wid = tid >> 5;
    int warp_m = wid & 3;
    int warp_n = wid >> 2;
    int bm = blockIdx.x * BM;
    int ntile = blockIdx.y;
    int wsel = ntile >> 2;
    const __half* WH = Whi + (size_t)wsel * wstride;
    const __half* WL = Wlo + (size_t)wsel * wstride;
    const float* bias = (wsel == 0) ? b0 : (wsel == 1 ? b1 : b2);
    __half* OutHi = (wsel == 0) ? oh0 : (wsel == 1 ? oh1 : oh2);
    __half* OutLo = (wsel == 0) ? ol0 : (wsel == 1 ? ol1 : ol2);
    int nbase = (ntile & 3) * 128;

    auto stage = [&](int s, int d) {
        int k0 = s * GBK;
        uint32_t base = sbase + d * BUF;
#pragma unroll
        for (int j = 0; j < A_ITER; j++) {
            int c = tid + j * 256;
            int row = c >> 3, sub = c & 7, plane = sub >> 2, i = sub & 3;
            uint32_t dst = base + SWZ128((uint32_t)(row * 128 + plane * 64 + i * 16));
            const __half* sp = plane ? Alo : Ahi;
            int gr = bm + row;
            const __half* src = sp + (size_t)gr * D + k0 + i * 8;
            cp_async16(dst, src, gr < M ? 16 : 0);
        }
#pragma unroll
        for (int j = 0; j < B_ITER; j++) {
            int c = tid + j * 256;
            int row = c >> 3, sub = c & 7, plane = sub >> 2, i = sub & 3;
            uint32_t dst = base + ABYTES +
                           SWZ128((uint32_t)(row * 128 + plane * 64 + i * 16));
            const __half* sp = plane ? WL : WH;
            const __half* src = sp + (size_t)(nbase + row) * D + k0 + i * 8;
            cp_async16(dst, src, 16);
        }
        CP_COMMIT();
    };

    float acc[MF][8][4];
#pragma unroll
    for (int i = 0; i < MF; i++)
#pragma unroll
        for (int j = 0; j < 8; j++)
#pragma unroll
            for (int k = 0; k < 4; k++) acc[i][j][k] = 0.f;

    stage(0, 0);
    stage(1, 1);

    for (int s = 0; s < NSTAGE; s++) {
        if (s == NSTAGE - 1) CP_WAIT(0); else CP_WAIT(1);
        __syncthreads();
        if (s + 2 < NSTAGE) stage(s + 2, (s + 2) % 3);

        uint32_t Abase = sbase + (s % 3) * BUF;
        uint32_t Bbase = Abase + ABYTES;
#pragma unroll
        for (int ks = 0; ks < 2; ks++) {
            uint32_t ah[MF][4], al[MF][4];
#pragma unroll
            for (int mf = 0; mf < MF; mf++) {
                int row = warp_m * (16 * MF) + mf * 16 + (lane & 15);
                uint32_t off =
                    (uint32_t)(row * 128 + ks * 32 + ((lane >> 4) << 4));
                ldsm4(ah[mf], Abase + SWZ128(off));
                ldsm4(al[mf], Abase + SWZ128(off + 64));
            }
#pragma unroll
            for (int np = 0; np < 4; np++) {
                int g = lane >> 3;
                int n = warp_n * 64 + np * 16 + ((g >> 1) << 3) + (lane & 7);
                uint32_t off = (uint32_t)(n * 128 + ks * 32 + ((g & 1) << 4));
                uint32_t rh[4], rl[4];
                ldsm4(rh, Bbase + SWZ128(off));
                ldsm4(rl, Bbase + SWZ128(off + 64));
#pragma unroll
                for (int mf = 0; mf < MF; mf++) {
                    mma16816(acc[mf][np * 2], ah[mf], rh);
                    mma16816(acc[mf][np * 2 + 1], ah[mf], rh + 2);
                    mma16816(acc[mf][np * 2], ah[mf], rl);
                    mma16816(acc[mf][np * 2 + 1], ah[mf], rl + 2);
                    mma16816(acc[mf][np * 2], al[mf], rh);
                    mma16816(acc[mf][np * 2 + 1], al[mf], rh + 2);
                }
            }
        }
    }

    // ---- epilogue
#pragma unroll
    for (int mf = 0; mf < MF; mf++) {
#pragma unroll
        for (int nf = 0; nf < 8; nf++) {
            int gc = nbase + warp_n * 64 + nf * 8 + (lane & 3) * 2;
            float2 bb = *reinterpret_cast<const float2*>(&bias[gc]);
            int r0 = bm + warp_m * (16 * MF) + mf * 16 + (lane >> 2);
#pragma unroll
            for (int hh = 0; hh < 2; hh++) {
                int gr = r0 + hh * 8;
                if (gr >= M) continue;
                float vx = acc[mf][nf][hh * 2 + 0] + bb.x;
                float vy = acc[mf][nf][hh * 2 + 1] + bb.y;
                if (HOUT) {
                    __half hx, hy, lx, ly;
                    split2(vx, hx, lx); split2(vy, hy, ly);
                    *reinterpret_cast<uint32_t*>(&OutHi[(size_t)gr * D + gc]) =
                        packh(hx, hy);
                    *reinterpret_cast<uint32_t*>(&OutLo[(size_t)gr * D + gc]) =
                        packh(lx, ly);
                } else {
                    if (resid) {
                        float2 rr = *reinterpret_cast<const float2*>(
                            &resid[(size_t)gr * D + gc]);
                        vx += rr.x; vy += rr.y;
                    }
                    float2 v; v.x = vx; v.y = vy;
                    *reinterpret_cast<float2*>(&o0[(size_t)gr * D + gc]) = v;
                }
            }
        }
    }
}

// ---------------------------------------------------------------------------
// split for attention output (g_att planes come from attn directly; this is
// only used nowhere now — kept for proj input which attn writes itself)
// ---------------------------------------------------------------------------

// ---------------------------------------------------------------------------
// mma attention: one block per (b,h), 8 warps, 2 CTAs/SM.
// ---------------------------------------------------------------------------
#define AT_PHI   0
#define AT_PLO   32768
#define AT_Q     0
#define AT_K     16384
#define AT_VTHI  65536
#define AT_VTLO  73728
#define AT_PMAX  81920
#define AT_PSUM  83968
#define AT_LINV  86016
#define AT_SMEM  86528

__global__ void __launch_bounds__(256, 2)
attn_mma(const float* __restrict__ attn_bias) {
    extern __shared__ __align__(128) char sm[];
    uint32_t sb = smem_to_u32(sm);
    int tid = threadIdx.x;
    int lane = tid & 31;
    int wid = tid >> 5;
    int bh = blockIdx.x;
    int b = bh >> 4;
    int h = bh & 15;
    int s0 = g_starts[b];
    int n = g_starts[b + 1] - s0;

    {
        int row = tid >> 1;
        int part = tid & 1;
        const __half* qp = part ? g_qlo : g_qhi;
        const __half* kp = part ? g_klo : g_khi;
        size_t src = (size_t)(s0 + row) * D + h * HS;
#pragma unroll
        for (int i = 0; i < 4; i++) {
            uint4 qv = make_uint4(0, 0, 0, 0), kv = make_uint4(0, 0, 0, 0);
            if (row < n) {
                qv = *reinterpret_cast<const uint4*>(&qp[src + i * 8]);
                kv = *reinterpret_cast<const uint4*>(&kp[src + i * 8]);
            }
            uint32_t off = SWZ128((uint32_t)(row * 128 + part * 64 + i * 16));
            *reinterpret_cast<uint4*>(sm + AT_Q + off) = qv;
            *reinterpret_cast<uint4*>(sm + AT_K + off) = kv;
        }
    }
    {
        int j = tid >> 1;
        int part = tid & 1;
        size_t src = (size_t)(s0 + j) * D + h * HS + part * 16;
#pragma unroll
        for (int rep = 0; rep < 2; rep++) {
            uint4 hv = make_uint4(0, 0, 0, 0), lv = make_uint4(0, 0, 0, 0);
            if (j < n) {
                hv = *reinterpret_cast<const uint4*>(&g_vhi[src + rep * 8]);
                lv = *reinterpret_cast<const uint4*>(&g_vlo[src + rep * 8]);
            }
            const __half* hp = reinterpret_cast<const __half*>(&hv);
            const __half* lp = reinterpret_cast<const __half*>(&lv);
#pragma unroll
            for (int i = 0; i < 8; i++) {
                int d = part * 16 + rep * 8 + i;
                uint32_t off = SWZ256((uint32_t)(d * 256 + j * 2));
                *reinterpret_cast<__half*>(sm + AT_VTHI + off) = hp[i];
                *reinterpret_cast<__half*>(sm + AT_VTLO + off) = lp[i];
            }
        }
    }
    __syncthreads();

    int warp_m = wid & 1;
    int warp_n = wid >> 1;
    float sc[4][4][4];
#pragma unroll
    for (int i = 0; i < 4; i++)
#pragma unroll
        for (int j = 0; j < 4; j++)
#pragma unroll
            for (int k = 0; k < 4; k++) sc[i][j][k] = 0.f;

#pragma unroll
    for (int ks = 0; ks < 2; ks++) {
        uint32_t ah[4][4], al[4][4];
#pragma unroll
        for (int mf = 0; mf < 4; mf++) {
            int row = warp_m * 64 + mf * 16 + (lane & 15);
            uint32_t off = (uint32_t)(row * 128 + ks * 32 + ((lane >> 4) << 4));
            ldsm4(ah[mf], sb + AT_Q + SWZ128(off));
            ldsm4(al[mf], sb + AT_Q + SWZ128(off + 64));
        }
        uint32_t bh2[4][2], bl2[4][2];
#pragma unroll
        for (int np = 0; np < 2; np++) {
            int g = lane >> 3;
            int nn = warp_n * 32 + np * 16 + ((g >> 1) << 3) + (lane & 7);
            uint32_t off = (uint32_t)(nn * 128 + ks * 32 + ((g & 1) << 4));
            uint32_t r[4];
            ldsm4(r, sb + AT_K + SWZ128(off));
            bh2[np * 2][0] = r[0]; bh2[np * 2][1] = r[1];
            bh2[np * 2 + 1][0] = r[2]; bh2[np * 2 + 1][1] = r[3];
            ldsm4(r, sb + AT_K + SWZ128(off + 64));
            bl2[np * 2][0] = r[0]; bl2[np * 2][1] = r[1];
            bl2[np * 2 + 1][0] = r[2]; bl2[np * 2 + 1][1] = r[3];
        }
#pragma unroll
        for (int mf = 0; mf < 4; mf++)
#pragma unroll
            for (int nf = 0; nf < 4; nf++) {
                mma16816(sc[mf][nf], ah[mf], bh2[nf]);
                mma16816(sc[mf][nf], ah[mf], bl2[nf]);
                mma16816(sc[mf][nf], al[mf], bh2[nf]);
            }
    }

    const float* bb = attn_bias + ((size_t)(b * NHEAD + h)) * MAXN * MAXN;
#pragma unroll
    for (int mf = 0; mf < 4; mf++) {
        int r0 = warp_m * 64 + mf * 16 + (lane >> 2);
#pragma unroll
        for (int nf = 0; nf < 4; nf++) {
            int c0 = warp_n * 32 + nf * 8 + (lane & 3) * 2;
#pragma unroll
            for (int hh = 0; hh < 2; hh++) {
                int r = r0 + hh * 8;
                float2 bv = *reinterpret_cast<const float2*>(&bb[r * MAXN + c0]);
                float v0 = sc[mf][nf][hh * 2] * ATT_SCALE + bv.x;
                float v1 = sc[mf][nf][hh * 2 + 1] * ATT_SCALE + bv.y;
                if (c0 >= n) v0 = -1e30f;
                if (c0 + 1 >= n) v1 = -1e30f;
                sc[mf][nf][hh * 2] = v0;
                sc[mf][nf][hh * 2 + 1] = v1;
            }
        }
    }

#pragma unroll
    for (int mf = 0; mf < 4; mf++)
#pragma unroll
        for (int hh = 0; hh < 2; hh++) {
            float mx = -1e30f;
#pragma unroll
            for (int nf = 0; nf < 4; nf++)
                mx = fmaxf(mx, fmaxf(sc[mf][nf][hh * 2], sc[mf][nf][hh * 2 + 1]));
            mx = fmaxf(mx, __shfl_xor_sync(0xffffffffu, mx, 1));
            mx = fmaxf(mx, __shfl_xor_sync(0xffffffffu, mx, 2));
            int row = warp_m * 64 + mf * 16 + (lane >> 2) + hh * 8;
            if ((lane & 3) == 0)
                *reinterpret_cast<float*>(sm + AT_PMAX + (row * 4 + warp_n) * 4) = mx;
        }
    __syncthreads();

#pragma unroll
    for (int mf = 0; mf < 4; mf++)
#pragma unroll
        for (int hh = 0; hh < 2; hh++) {
            int row = warp_m * 64 + mf * 16 + (lane >> 2) + hh * 8;
            float4 m4 = *reinterpret_cast<float4*>(sm + AT_PMAX + row * 16);
            float m = fmaxf(fmaxf(m4.x, m4.y), fmaxf(m4.z, m4.w));
            float ssum = 0.f;
#pragma unroll
            for (int nf = 0; nf < 4; nf++) {
                float p0 = __expf(sc[mf][nf][hh * 2] - m);
                float p1 = __expf(sc[mf][nf][hh * 2 + 1] - m);
                ssum += p0 + p1;
                int c0 = warp_n * 32 + nf * 8 + (lane & 3) * 2;
                __half h0, h1, l0, l1;
                split2(p0, h0, l0); split2(p1, h1, l1);
                uint32_t off = (uint32_t)(row * 256 + c0 * 2);
                *reinterpret_cast<uint32_t*>(sm + AT_PHI + SWZ256(off)) = packh(h0, h1);
                *reinterpret_cast<uint32_t*>(sm + AT_PLO + SWZ256(off)) = packh(l0, l1);
            }
            ssum += __shfl_xor_sync(0xffffffffu, ssum, 1);
            ssum += __shfl_xor_sync(0xffffffffu, ssum, 2);
            if ((lane & 3) == 0)
                *reinterpret_cast<float*>(sm + AT_PSUM + (row * 4 + warp_n) * 4) = ssum;
        }
    __syncthreads();

    if (tid < 128) {
        float4 s4 = *reinterpret_cast<float4*>(sm + AT_PSUM + tid * 16);
        float l = s4.x + s4.y + s4.z + s4.w;
        *reinterpret_cast<float*>(sm + AT_LINV + tid * 4) = 1.f / l;
    }
    __syncthreads();

    float oc[4][4];
#pragma unroll
    for (int j = 0; j < 4; j++)
#pragma unroll
        for (int k = 0; k < 4; k++) oc[j][k] = 0.f;

#pragma unroll
    for (int ks = 0; ks < 8; ks++) {
        uint32_t ph[4], pl[4];
        {
            int row = wid * 16 + (lane & 15);
            uint32_t off = (uint32_t)(row * 256 + ks * 32 + ((lane >> 4) << 4));
            ldsm4(ph, sb + AT_PHI + SWZ256(off));
            ldsm4(pl, sb + AT_PLO + SWZ256(off));
        }
        uint32_t vh[4][2], vl[4][2];
#pragma unroll
        for (int np = 0; np < 2; np++) {
            int g = lane >> 3;
            int nn = np * 16 + ((g >> 1) << 3) + (lane & 7);
            uint32_t off = (uint32_t)(nn * 256 + ks * 32 + ((g & 1) << 4));
            uint32_t r[4];
            ldsm4(r, sb + AT_VTHI + SWZ256(off));
            vh[np * 2][0] = r[0]; vh[np * 2][1] = r[1];
            vh[np * 2 + 1][0] = r[2]; vh[np * 2 + 1][1] = r[3];
            ldsm4(r, sb + AT_VTLO + SWZ256(off));
            vl[np * 2][0] = r[0]; vl[np * 2][1] = r[1];
            vl[np * 2 + 1][0] = r[2]; vl[np * 2 + 1][1] = r[3];
        }
#pragma unroll
        for (int nf = 0; nf < 4; nf++) {
            mma16816(oc[nf], ph, vh[nf]);
            mma16816(oc[nf], ph, vl[nf]);
            mma16816(oc[nf], pl, vh[nf]);
        }
    }

    int r0 = wid * 16 + (lane >> 2);
#pragma unroll
    for (int hh = 0; hh < 2; hh++) {
        int row = r0 + hh * 8;
        if (row >= n) continue;
        float linv = *reinterpret_cast<float*>(sm + AT_LINV + row * 4);
        size_t base = (size_t)(s0 + row) * D + h * HS;
#pragma unroll
        for (int nf = 0; nf < 4; nf++) {
            int d0 = nf * 8 + (lane & 3) * 2;
            float o0 = oc[nf][hh * 2] * linv;
            float o1 = oc[nf][hh * 2 + 1] * linv;
            __half h0, h1, l0, l1;
            split2(o0, h0, l0); split2(o1, h1, l1);
            *reinterpret_cast<uint32_t*>(&g_ahi[base + d0]) = packh(h0, h1);
            *reinterpret_cast<uint32_t*>(&g_alo[base + d0]) = packh(l0, l1);
        }
    }
}

// ---------------------------------------------------------------------------
// LayerNorm
// ---------------------------------------------------------------------------
__global__ void __launch_bounds__(256)
ln_kernel(const float* __restrict__ ln_w, const float* __restrict__ ln_b,
          float* __restrict__ out) {
    int row = blockIdx.x;
    const float* y = g_y + (size_t)row * D;
    int tid = threadIdx.x;

    float v0 = y[tid];
    float v1 = y[tid + 256];
    float s = v0 + v1;
    float q = v0 * v0 + v1 * v1;
#pragma unroll
    for (int off = 16; off; off >>= 1) {
        s += __shfl_down_sync(0xffffffffu, s, off);
        q += __shfl_down_sync(0xffffffffu, q, off);
    }
    __shared__ float rs[8], rq[8];
    __shared__ float s_mu, s_rstd;
    if ((tid & 31) == 0) { rs[tid >> 5] = s; rq[tid >> 5] = q; }
    __syncthreads();
    if (tid == 0) {
        float S = 0.f, Q = 0.f;
#pragma unroll
        for (int i = 0; i < 8; i++) { S += rs[i]; Q += rq[i]; }
        float mu = S * (1.f / D);
        float var = Q * (1.f / D) - mu * mu;
        s_mu = mu;
        s_rstd = rsqrtf(var + LN_EPS);
    }
    __syncthreads();
    float mu = s_mu, r = s_rstd;
    out[(size_t)row * D + tid] = (v0 - mu) * r * ln_w[tid] + ln_b[tid];
    out[(size_t)row * D + tid + 256] =
        (v1 - mu) * r * ln_w[tid + 256] + ln_b[tid + 256];
}

// ---------------------------------------------------------------------------
extern "C" void kernel_launch(void* const* d_in, const int* in_sizes, int n_in,
                              void* d_out, int out_size) {
    const float* x         = (const float*)d_in[0];
    const float* attn_bias = (const float*)d_in[1];
    const float* Wq = (const float*)d_in[2];
    const float* bq = (const float*)d_in[3];
    const float* Wk = (const float*)d_in[4];
    const float* bk = (const float*)d_in[5];
    const float* Wv = (const float*)d_in[6];
    const float* bv = (const float*)d_in[7];
    const float* Wp = (const float*)d_in[8];
    const float* bp = (const float*)d_in[9];
    const float* ln_w = (const float*)d_in[10];
    const float* ln_b = (const float*)d_in[11];
    const int*   batch = (const int*)d_in[12];

    int N = in_sizes[12];
    float* out = (float*)d_out;

    float *yp;
    __half *whi, *wlo, *ahi, *alo, *qhi, *qlo, *khi, *klo, *vhi, *vlo;
    cudaGetSymbolAddress((void**)&yp, g_y);
    cudaGetSymbolAddress((void**)&whi, g_whi);
    cudaGetSymbolAddress((void**)&wlo, g_wlo);
    cudaGetSymbolAddress((void**)&ahi, g_ahi);
    cudaGetSymbolAddress((void**)&alo, g_alo);
    cudaGetSymbolAddress((void**)&qhi, g_qhi);
    cudaGetSymbolAddress((void**)&qlo, g_qlo);
    cudaGetSymbolAddress((void**)&khi, g_khi);
    cudaGetSymbolAddress((void**)&klo, g_klo);
    cudaGetSymbolAddress((void**)&vhi, g_vhi);
    cudaGetSymbolAddress((void**)&vlo, g_vlo);

    const int smem_qkv = 3 * (128 * 128 + 128 * 128);   // 98304
    const int smem_prj = 3 * (64 * 128 + 128 * 128);    // 73728
    cudaFuncSetAttribute(mma_gemm<128, 1>,
                         cudaFuncAttributeMaxDynamicSharedMemorySize, smem_qkv);
    cudaFuncSetAttribute(mma_gemm<64, 0>,
                         cudaFuncAttributeMaxDynamicSharedMemorySize, smem_prj);
    cudaFuncSetAttribute(attn_mma,
                         cudaFuncAttributeMaxDynamicSharedMemorySize, AT_SMEM);

    // Fused prologue: split x, split W, segment starts
    int n4 = N * D / 4;
    int total = n4 + 4 * WELEM / 4 + N;
    prep_kernel<<<(total + 255) / 256, 256>>>(x, Wq, Wk, Wv, Wp, batch, N);

    // Fused QKV: grid.y 0-3 -> Wq, 4-7 -> Wk, 8-11 -> Wv
    mma_gemm<128, 1><<<dim3((N + 127) / 128, 12), 256, smem_qkv>>>(
        ahi, alo, whi, wlo, WELEM, bq, bk, bv, nullptr,
        qhi, qlo, khi, klo, vhi, vlo, nullptr, N);

    attn_mma<<<NB * NHEAD, 256, AT_SMEM>>>(attn_bias);

    // Output projection + bias + residual (W plane 3)
    mma_gemm<64, 0><<<dim3((N + 63) / 64, 4), 256, smem_prj>>>(
        ahi, alo, whi + 3 * WELEM, wlo + 3 * WELEM, 0,
        bp, bp, bp, yp,
        nullptr, nullptr, nullptr, nullptr, nullptr, nullptr, x, N);

    ln_kernel<<<N, 256>>>(ln_w, ln_b, out);
}

// round 15
// speedup vs baseline: 1.3860x; 1.1444x over previous
#include <cuda_runtime.h>
#include <cuda_fp16.h>
#include <math.h>
#include <stdint.h>

// Problem constants
#define D     512
#define NHEAD 16
#define HS    32
#define NB    64
#define MAXN  128
#define ATT_SCALE 0.17677669529663687f
#define LN_EPS 1e-5f
#define MAX_ROWS 8192
#define WELEM (512 * 512)

// Scratch
__device__ float g_y[MAX_ROWS * D];
__device__ int   g_starts[NB + 1];
__device__ __half g_whi[4 * WELEM];
__device__ __half g_wlo[4 * WELEM];
__device__ __half g_ahi[MAX_ROWS * D];
__device__ __half g_alo[MAX_ROWS * D];
__device__ __half g_qhi[MAX_ROWS * D];
__device__ __half g_qlo[MAX_ROWS * D];
__device__ __half g_khi[MAX_ROWS * D];
__device__ __half g_klo[MAX_ROWS * D];
__device__ __half g_vhi[MAX_ROWS * D];
__device__ __half g_vlo[MAX_ROWS * D];

#define SWZ128(o) ((o) ^ (((o) >> 3) & 0x70u))
#define SWZ256(o) ((o) ^ (((o) >> 4) & 0x70u))

__device__ __forceinline__ uint32_t smem_to_u32(const void* p) {
    uint32_t a;
    asm("{ .reg .u64 t; cvta.to.shared.u64 t, %1; cvt.u32.u64 %0, t; }"
        : "=r"(a) : "l"(p));
    return a;
}
__device__ __forceinline__ void ldsm4(uint32_t* r, uint32_t addr) {
    asm volatile("ldmatrix.sync.aligned.m8n8.x4.shared.b16 {%0,%1,%2,%3}, [%4];"
                 : "=r"(r[0]), "=r"(r[1]), "=r"(r[2]), "=r"(r[3]) : "r"(addr));
}
// non-volatile: register-only op, ptxas may schedule freely
__device__ __forceinline__ void mma16816(float* c, const uint32_t* a,
                                         const uint32_t* b) {
    asm("mma.sync.aligned.m16n8k16.row.col.f32.f16.f16.f32 "
        "{%0,%1,%2,%3}, {%4,%5,%6,%7}, {%8,%9}, {%0,%1,%2,%3};"
        : "+f"(c[0]), "+f"(c[1]), "+f"(c[2]), "+f"(c[3])
        : "r"(a[0]), "r"(a[1]), "r"(a[2]), "r"(a[3]), "r"(b[0]), "r"(b[1]));
}
__device__ __forceinline__ uint32_t packh(__half a, __half b) {
    __half2 h = __halves2half2(a, b);
    return *reinterpret_cast<uint32_t*>(&h);
}
__device__ __forceinline__ void split2(float x, __half& hi, __half& lo) {
    hi = __float2half_rn(x);
    lo = __float2half_rn(x - __half2float(hi));
}
__device__ __forceinline__ void cp_async16(uint32_t dst, const void* src, int sz) {
    asm volatile("cp.async.cg.shared.global [%0], [%1], 16, %2;"
                 :: "r"(dst), "l"(src), "r"(sz) : "memory");
}
#define CP_COMMIT() asm volatile("cp.async.commit_group;" ::: "memory")
#define CP_WAIT(n)  asm volatile("cp.async.wait_group %0;" :: "n"(n) : "memory")

// ---------------------------------------------------------------------------
// Fused prologue: starts + W split + x split, one launch.
// ---------------------------------------------------------------------------
__global__ void prep_kernel(const float* __restrict__ x,
                            const float* __restrict__ Wq,
                            const float* __restrict__ Wk,
                            const float* __restrict__ Wv,
                            const float* __restrict__ Wp,
                            const int* __restrict__ batch, int N) {
    int n4 = N * D / 4;
    const int w4 = 4 * WELEM / 4;
    int i = blockIdx.x * blockDim.x + threadIdx.x;
    if (i < n4) {
        float4 v = reinterpret_cast<const float4*>(x)[i];
        __half hx, hy, hz, hw, lx, ly, lz, lw;
        split2(v.x, hx, lx); split2(v.y, hy, ly);
        split2(v.z, hz, lz); split2(v.w, hw, lw);
        uint2 hi, lo;
        hi.x = packh(hx, hy); hi.y = packh(hz, hw);
        lo.x = packh(lx, ly); lo.y = packh(lz, lw);
        reinterpret_cast<uint2*>(g_ahi)[i] = hi;
        reinterpret_cast<uint2*>(g_alo)[i] = lo;
    } else if (i < n4 + w4) {
        int j = i - n4;
        int j4 = j * 4;
        int w = j4 >> 18;
        int off = j4 & (WELEM - 1);
        const float* src = (w == 0) ? Wq : (w == 1) ? Wk : (w == 2) ? Wv : Wp;
        float4 v = *reinterpret_cast<const float4*>(&src[off]);
        __half hx, hy, hz, hw, lx, ly, lz, lw;
        split2(v.x, hx, lx); split2(v.y, hy, ly);
        split2(v.z, hz, lz); split2(v.w, hw, lw);
        uint2 hi, lo;
        hi.x = packh(hx, hy); hi.y = packh(hz, hw);
        lo.x = packh(lx, ly); lo.y = packh(lz, lw);
        reinterpret_cast<uint2*>(g_whi)[j] = hi;
        reinterpret_cast<uint2*>(g_wlo)[j] = lo;
    } else if (i < n4 + w4 + N) {
        int j = i - n4 - w4;
        int b = batch[j];
        if (j == 0 || batch[j - 1] != b) g_starts[b] = j;
        if (j == N - 1) g_starts[NB] = N;
    }
}

// ---------------------------------------------------------------------------
// split-fp16 2-term mma.sync GEMM: (Ahi+Alo) x Whi  (W-lo dropped; ~2.4e-4
// rel error per GEMM, calibrated against the 3-term baseline).
// Block tile BM x 128, 256 thr = 8 warps (4m x 2n), 2 CTAs/SM, cp.async x3.
// ---------------------------------------------------------------------------
#define GBK 32
#define NSTAGE (D / GBK)

template <int BM, int HOUT>
__global__ void __launch_bounds__(256, 2)
mma_gemm(const __half* __restrict__ Ahi, const __half* __restrict__ Alo,
         const __half* __restrict__ Whi, const __half* __restrict__ Wlo,
         int wstride,
         const float* __restrict__ b0, const float* __restrict__ b1,
         const float* __restrict__ b2,
         float* __restrict__ o0,
         __half* __restrict__ oh0, __half* __restrict__ ol0,
         __half* __restrict__ oh1, __half* __restrict__ ol1,
         __half* __restrict__ oh2, __half* __restrict__ ol2,
         const float* __restrict__ resid, int M) {
    constexpr int MF = BM / 64;
    constexpr int ABYTES = BM * 128;
    constexpr int BBYTES = 128 * 128;
    constexpr int BUF = ABYTES + BBYTES;
    constexpr int A_ITER = (ABYTES / 16) / 256;
    constexpr int B_ITER = (BBYTES / 16) / 256;
    extern __shared__ __align__(128) char smem[];
    uint32_t sbase = smem_to_u32(smem);
    int tid = threadIdx.x;
    int lane = tid & 31;
    int wid = tid >> 5;
    int warp_m = wid & 3;
    int warp_n = wid >> 2;
    int bm = blockIdx.x * BM;
    int ntile = blockIdx.y;
    int wsel = ntile >> 2;
    const __half* WH = Whi + (size_t)wsel * wstride;
    const __half* WL = Wlo + (size_t)wsel * wstride;
    const float* bias = (wsel == 0) ? b0 : (wsel == 1 ? b1 : b2);
    __half* OutHi = (wsel == 0) ? oh0 : (wsel == 1 ? oh1 : oh2);
    __half* OutLo = (wsel == 0) ? ol0 : (wsel == 1 ? ol1 : ol2);
    int nbase = (ntile & 3) * 128;

    auto stage = [&](int s, int d) {
        int k0 = s * GBK;
        uint32_t base = sbase + d * BUF;
#pragma unroll
        for (int j = 0; j < A_ITER; j++) {
            int c = tid + j * 256;
            int row = c >> 3, sub = c & 7, plane = sub >> 2, i = sub & 3;
            uint32_t dst = base + SWZ128((uint32_t)(row * 128 + plane * 64 + i * 16));
            const __half* sp = plane ? Alo : Ahi;
            int gr = bm + row;
            const __half* src = sp + (size_t)gr * D + k0 + i * 8;
            cp_async16(dst, src, gr < M ? 16 : 0);
        }
#pragma unroll
        for (int j = 0; j < B_ITER; j++) {
            int c = tid + j * 256;
            int row = c >> 3, sub = c & 7, plane = sub >> 2, i = sub & 3;
            uint32_t dst = base + ABYTES +
                           SWZ128((uint32_t)(row * 128 + plane * 64 + i * 16));
            const __half* sp = plane ? WL : WH;
            const __half* src = sp + (size_t)(nbase + row) * D + k0 + i * 8;
            cp_async16(dst, src, 16);
        }
        CP_COMMIT();
    };

    float acc[MF][8][4];
#pragma unroll
    for (int i = 0; i < MF; i++)
#pragma unroll
        for (int j = 0; j < 8; j++)
#pragma unroll
            for (int k = 0; k < 4; k++) acc[i][j][k] = 0.f;

    stage(0, 0);
    stage(1, 1);

    for (int s = 0; s < NSTAGE; s++) {
        if (s == NSTAGE - 1) CP_WAIT(0); else CP_WAIT(1);
        __syncthreads();
        if (s + 2 < NSTAGE) stage(s + 2, (s + 2) % 3);

        uint32_t Abase = sbase + (s % 3) * BUF;
        uint32_t Bbase = Abase + ABYTES;
#pragma unroll
        for (int ks = 0; ks < 2; ks++) {
            uint32_t ah[MF][4], al[MF][4];
#pragma unroll
            for (int mf = 0; mf < MF; mf++) {
                int row = warp_m * (16 * MF) + mf * 16 + (lane & 15);
                uint32_t off =
                    (uint32_t)(row * 128 + ks * 32 + ((lane >> 4) << 4));
                ldsm4(ah[mf], Abase + SWZ128(off));
                ldsm4(al[mf], Abase + SWZ128(off + 64));
            }
#pragma unroll
            for (int np = 0; np < 4; np++) {
                int g = lane >> 3;
                int n = warp_n * 64 + np * 16 + ((g >> 1) << 3) + (lane & 7);
                uint32_t off = (uint32_t)(n * 128 + ks * 32 + ((g & 1) << 4));
                uint32_t rh[4];
                ldsm4(rh, Bbase + SWZ128(off));
#pragma unroll
                for (int mf = 0; mf < MF; mf++) {
                    mma16816(acc[mf][np * 2], ah[mf], rh);
                    mma16816(acc[mf][np * 2 + 1], ah[mf], rh + 2);
                    mma16816(acc[mf][np * 2], al[mf], rh);
                    mma16816(acc[mf][np * 2 + 1], al[mf], rh + 2);
                }
            }
        }
    }

    // ---- epilogue
#pragma unroll
    for (int mf = 0; mf < MF; mf++) {
#pragma unroll
        for (int nf = 0; nf < 8; nf++) {
            int gc = nbase + warp_n * 64 + nf * 8 + (lane & 3) * 2;
            float2 bb = *reinterpret_cast<const float2*>(&bias[gc]);
            int r0 = bm + warp_m * (16 * MF) + mf * 16 + (lane >> 2);
#pragma unroll
            for (int hh = 0; hh < 2; hh++) {
                int gr = r0 + hh * 8;
                if (gr >= M) continue;
                float vx = acc[mf][nf][hh * 2 + 0] + bb.x;
                float vy = acc[mf][nf][hh * 2 + 1] + bb.y;
                if (HOUT) {
                    __half hx, hy, lx, ly;
                    split2(vx, hx, lx); split2(vy, hy, ly);
                    *reinterpret_cast<uint32_t*>(&OutHi[(size_t)gr * D + gc]) =
                        packh(hx, hy);
                    *reinterpret_cast<uint32_t*>(&OutLo[(size_t)gr * D + gc]) =
                        packh(lx, ly);
                } else {
                    if (resid) {
                        float2 rr = *reinterpret_cast<const float2*>(
                            &resid[(size_t)gr * D + gc]);
                        vx += rr.x; vy += rr.y;
                    }
                    float2 v; v.x = vx; v.y = vy;
                    *reinterpret_cast<float2*>(&o0[(size_t)gr * D + gc]) = v;
                }
            }
        }
    }
}

// ---------------------------------------------------------------------------
// mma attention (R13-proven 3-term): one block per (b,h), 8 warps, 2 CTAs/SM.
// ---------------------------------------------------------------------------
#define AT_PHI   0
#define AT_PLO   32768
#define AT_Q     0
#define AT_K     16384
#define AT_VTHI  65536
#define AT_VTLO  73728
#define AT_PMAX  81920
#define AT_PSUM  83968
#define AT_LINV  86016
#define AT_SMEM  86528

__global__ void __launch_bounds__(256, 2)
attn_mma(const float* __restrict__ attn_bias) {
    extern __shared__ __align__(128) char sm[];
    uint32_t sb = smem_to_u32(sm);
    int tid = threadIdx.x;
    int lane = tid & 31;
    int wid = tid >> 5;
    int bh = blockIdx.x;
    int b = bh >> 4;
    int h = bh & 15;
    int s0 = g_starts[b];
    int n = g_starts[b + 1] - s0;

    {
        int row = tid >> 1;
        int part = tid & 1;
        const __half* qp = part ? g_qlo : g_qhi;
        const __half* kp = part ? g_klo : g_khi;
        size_t src = (size_t)(s0 + row) * D + h * HS;
#pragma unroll
        for (int i = 0; i < 4; i++) {
            uint4 qv = make_uint4(0, 0, 0, 0), kv = make_uint4(0, 0, 0, 0);
            if (row < n) {
                qv = *reinterpret_cast<const uint4*>(&qp[src + i * 8]);
                kv = *reinterpret_cast<const uint4*>(&kp[src + i * 8]);
            }
            uint32_t off = SWZ128((uint32_t)(row * 128 + part * 64 + i * 16));
            *reinterpret_cast<uint4*>(sm + AT_Q + off) = qv;
            *reinterpret_cast<uint4*>(sm + AT_K + off) = kv;
        }
    }
    {
        int j = tid >> 1;
        int part = tid & 1;
        size_t src = (size_t)(s0 + j) * D + h * HS + part * 16;
#pragma unroll
        for (int rep = 0; rep < 2; rep++) {
            uint4 hv = make_uint4(0, 0, 0, 0), lv = make_uint4(0, 0, 0, 0);
            if (j < n) {
                hv = *reinterpret_cast<const uint4*>(&g_vhi[src + rep * 8]);
                lv = *reinterpret_cast<const uint4*>(&g_vlo[src + rep * 8]);
            }
            const __half* hp = reinterpret_cast<const __half*>(&hv);
            const __half* lp = reinterpret_cast<const __half*>(&lv);
#pragma unroll
            for (int i = 0; i < 8; i++) {
                int d = part * 16 + rep * 8 + i;
                uint32_t off = SWZ256((uint32_t)(d * 256 + j * 2));
                *reinterpret_cast<__half*>(sm + AT_VTHI + off) = hp[i];
                *reinterpret_cast<__half*>(sm + AT_VTLO + off) = lp[i];
            }
        }
    }
    __syncthreads();

    int warp_m = wid & 1;
    int warp_n = wid >> 1;
    float sc[4][4][4];
#pragma unroll
    for (int i = 0; i < 4; i++)
#pragma unroll
        for (int j = 0; j < 4; j++)
#pragma unroll
            for (int k = 0; k < 4; k++) sc[i][j][k] = 0.f;

#pragma unroll
    for (int ks = 0; ks < 2; ks++) {
        uint32_t ah[4][4], al[4][4];
#pragma unroll
        for (int mf = 0; mf < 4; mf++) {
            int row = warp_m * 64 + mf * 16 + (lane & 15);
            uint32_t off = (uint32_t)(row * 128 + ks * 32 + ((lane >> 4) << 4));
            ldsm4(ah[mf], sb + AT_Q + SWZ128(off));
            ldsm4(al[mf], sb + AT_Q + SWZ128(off + 64));
        }
        uint32_t bh2[4][2], bl2[4][2];
#pragma unroll
        for (int np = 0; np < 2; np++) {
            int g = lane >> 3;
            int nn = warp_n * 32 + np * 16 + ((g >> 1) << 3) + (lane & 7);
            uint32_t off = (uint32_t)(nn * 128 + ks * 32 + ((g & 1) << 4));
            uint32_t r[4];
            ldsm4(r, sb + AT_K + SWZ128(off));
            bh2[np * 2][0] = r[0]; bh2[np * 2][1] = r[1];
            bh2[np * 2 + 1][0] = r[2]; bh2[np * 2 + 1][1] = r[3];
            ldsm4(r, sb + AT_K + SWZ128(off + 64));
            bl2[np * 2][0] = r[0]; bl2[np * 2][1] = r[1];
            bl2[np * 2 + 1][0] = r[2]; bl2[np * 2 + 1][1] = r[3];
        }
#pragma unroll
        for (int mf = 0; mf < 4; mf++)
#pragma unroll
            for (int nf = 0; nf < 4; nf++) {
                mma16816(sc[mf][nf], ah[mf], bh2[nf]);
                mma16816(sc[mf][nf], ah[mf], bl2[nf]);
                mma16816(sc[mf][nf], al[mf], bh2[nf]);
            }
    }

    const float* bb = attn_bias + ((size_t)(b * NHEAD + h)) * MAXN * MAXN;
#pragma unroll
    for (int mf = 0; mf < 4; mf++) {
        int r0 = warp_m * 64 + mf * 16 + (lane >> 2);
#pragma unroll
        for (int nf = 0; nf < 4; nf++) {
            int c0 = warp_n * 32 + nf * 8 + (lane & 3) * 2;
#pragma unroll
            for (int hh = 0; hh < 2; hh++) {
                int r = r0 + hh * 8;
                float2 bv = *reinterpret_cast<const float2*>(&bb[r * MAXN + c0]);
                float v0 = sc[mf][nf][hh * 2] * ATT_SCALE + bv.x;
                float v1 = sc[mf][nf][hh * 2 + 1] * ATT_SCALE + bv.y;
                if (c0 >= n) v0 = -1e30f;
                if (c0 + 1 >= n) v1 = -1e30f;
                sc[mf][nf][hh * 2] = v0;
                sc[mf][nf][hh * 2 + 1] = v1;
            }
        }
    }

#pragma unroll
    for (int mf = 0; mf < 4; mf++)
#pragma unroll
        for (int hh = 0; hh < 2; hh++) {
            float mx = -1e30f;
#pragma unroll
            for (int nf = 0; nf < 4; nf++)
                mx = fmaxf(mx, fmaxf(sc[mf][nf][hh * 2], sc[mf][nf][hh * 2 + 1]));
            mx = fmaxf(mx, __shfl_xor_sync(0xffffffffu, mx, 1));
            mx = fmaxf(mx, __shfl_xor_sync(0xffffffffu, mx, 2));
            int row = warp_m * 64 + mf * 16 + (lane >> 2) + hh * 8;
            if ((lane & 3) == 0)
                *reinterpret_cast<float*>(sm + AT_PMAX + (row * 4 + warp_n) * 4) = mx;
        }
    __syncthreads();

#pragma unroll
    for (int mf = 0; mf < 4; mf++)
#pragma unroll
        for (int hh = 0; hh < 2; hh++) {
            int row = warp_m * 64 + mf * 16 + (lane >> 2) + hh * 8;
            float4 m4 = *reinterpret_cast<float4*>(sm + AT_PMAX + row * 16);
            float m = fmaxf(fmaxf(m4.x, m4.y), fmaxf(m4.z, m4.w));
            float ssum = 0.f;
#pragma unroll
            for (int nf = 0; nf < 4; nf++) {
                float p0 = __expf(sc[mf][nf][hh * 2] - m);
                float p1 = __expf(sc[mf][nf][hh * 2 + 1] - m);
                ssum += p0 + p1;
                int c0 = warp_n * 32 + nf * 8 + (lane & 3) * 2;
                __half h0, h1, l0, l1;
                split2(p0, h0, l0); split2(p1, h1, l1);
                uint32_t off = (uint32_t)(row * 256 + c0 * 2);
                *reinterpret_cast<uint32_t*>(sm + AT_PHI + SWZ256(off)) = packh(h0, h1);
                *reinterpret_cast<uint32_t*>(sm + AT_PLO + SWZ256(off)) = packh(l0, l1);
            }
            ssum += __shfl_xor_sync(0xffffffffu, ssum, 1);
            ssum += __shfl_xor_sync(0xffffffffu, ssum, 2);
            if ((lane & 3) == 0)
                *reinterpret_cast<float*>(sm + AT_PSUM + (row * 4 + warp_n) * 4) = ssum;
        }
    __syncthreads();

    if (tid < 128) {
        float4 s4 = *reinterpret_cast<float4*>(sm + AT_PSUM + tid * 16);
        float l = s4.x + s4.y + s4.z + s4.w;
        *reinterpret_cast<float*>(sm + AT_LINV + tid * 4) = 1.f / l;
    }
    __syncthreads();

    float oc[4][4];
#pragma unroll
    for (int j = 0; j < 4; j++)
#pragma unroll
        for (int k = 0; k < 4; k++) oc[j][k] = 0.f;

#pragma unroll
    for (int ks = 0; ks < 8; ks++) {
        uint32_t ph[4], pl[4];
        {
            int row = wid * 16 + (lane & 15);
            uint32_t off = (uint32_t)(row * 256 + ks * 32 + ((lane >> 4) << 4));
            ldsm4(ph, sb + AT_PHI + SWZ256(off));
            ldsm4(pl, sb + AT_PLO + SWZ256(off));
        }
        uint32_t vh[4][2], vl[4][2];
#pragma unroll
        for (int np = 0; np < 2; np++) {
            int g = lane >> 3;
            int nn = np * 16 + ((g >> 1) << 3) + (lane & 7);
            uint32_t off = (uint32_t)(nn * 256 + ks * 32 + ((g & 1) << 4));
            uint32_t r[4];
            ldsm4(r, sb + AT_VTHI + SWZ256(off));
            vh[np * 2][0] = r[0]; vh[np * 2][1] = r[1];
            vh[np * 2 + 1][0] = r[2]; vh[np * 2 + 1][1] = r[3];
            ldsm4(r, sb + AT_VTLO + SWZ256(off));
            vl[np * 2][0] = r[0]; vl[np * 2][1] = r[1];
            vl[np * 2 + 1][0] = r[2]; vl[np * 2 + 1][1] = r[3];
        }
#pragma unroll
        for (int nf = 0; nf < 4; nf++) {
            mma16816(oc[nf], ph, vh[nf]);
            mma16816(oc[nf], ph, vl[nf]);
            mma16816(oc[nf], pl, vh[nf]);
        }
    }

    int r0 = wid * 16 + (lane >> 2);
#pragma unroll
    for (int hh = 0; hh < 2; hh++) {
        int row = r0 + hh * 8;
        if (row >= n) continue;
        float linv = *reinterpret_cast<float*>(sm + AT_LINV + row * 4);
        size_t base = (size_t)(s0 + row) * D + h * HS;
#pragma unroll
        for (int nf = 0; nf < 4; nf++) {
            int d0 = nf * 8 + (lane & 3) * 2;
            float o0 = oc[nf][hh * 2] * linv;
            float o1 = oc[nf][hh * 2 + 1] * linv;
            __half h0, h1, l0, l1;
            split2(o0, h0, l0); split2(o1, h1, l1);
            *reinterpret_cast<uint32_t*>(&g_ahi[base + d0]) = packh(h0, h1);
            *reinterpret_cast<uint32_t*>(&g_alo[base + d0]) = packh(l0, l1);
        }
    }
}

// ---------------------------------------------------------------------------
// LayerNorm
// ---------------------------------------------------------------------------
__global__ void __launch_bounds__(256)
ln_kernel(const float* __restrict__ ln_w, const float* __restrict__ ln_b,
          float* __restrict__ out) {
    int row = blockIdx.x;
    const float* y = g_y + (size_t)row * D;
    int tid = threadIdx.x;

    float v0 = y[tid];
    float v1 = y[tid + 256];
    float s = v0 + v1;
    float q = v0 * v0 + v1 * v1;
#pragma unroll
    for (int off = 16; off; off >>= 1) {
        s += __shfl_down_sync(0xffffffffu, s, off);
        q += __shfl_down_sync(0xffffffffu, q, off);
    }
    __shared__ float rs[8], rq[8];
    __shared__ float s_mu, s_rstd;
    if ((tid & 31) == 0) { rs[tid >> 5] = s; rq[tid >> 5] = q; }
    __syncthreads();
    if (tid == 0) {
        float S = 0.f, Q = 0.f;
#pragma unroll
        for (int i = 0; i < 8; i++) { S += rs[i]; Q += rq[i]; }
        float mu = S * (1.f / D);
        float var = Q * (1.f / D) - mu * mu;
        s_mu = mu;
        s_rstd = rsqrtf(var + LN_EPS);
    }
    __syncthreads();
    float mu = s_mu, r = s_rstd;
    out[(size_t)row * D + tid] = (v0 - mu) * r * ln_w[tid] + ln_b[tid];
    out[(size_t)row * D + tid + 256] =
        (v1 - mu) * r * ln_w[tid + 256] + ln_b[tid + 256];
}

// ---------------------------------------------------------------------------
extern "C" void kernel_launch(void* const* d_in, const int* in_sizes, int n_in,
                              void* d_out, int out_size) {
    const float* x         = (const float*)d_in[0];
    const float* attn_bias = (const float*)d_in[1];
    const float* Wq = (const float*)d_in[2];
    const float* bq = (const float*)d_in[3];
    const float* Wk = (const float*)d_in[4];
    const float* bk = (const float*)d_in[5];
    const float* Wv = (const float*)d_in[6];
    const float* bv = (const float*)d_in[7];
    const float* Wp = (const float*)d_in[8];
    const float* bp = (const float*)d_in[9];
    const float* ln_w = (const float*)d_in[10];
    const float* ln_b = (const float*)d_in[11];
    const int*   batch = (const int*)d_in[12];

    int N = in_sizes[12];
    float* out = (float*)d_out;

    float *yp;
    __half *whi, *wlo, *ahi, *alo, *qhi, *qlo, *khi, *klo, *vhi, *vlo;
    cudaGetSymbolAddress((void**)&yp, g_y);
    cudaGetSymbolAddress((void**)&whi, g_whi);
    cudaGetSymbolAddress((void**)&wlo, g_wlo);
    cudaGetSymbolAddress((void**)&ahi, g_ahi);
    cudaGetSymbolAddress((void**)&alo, g_alo);
    cudaGetSymbolAddress((void**)&qhi, g_qhi);
    cudaGetSymbolAddress((void**)&qlo, g_qlo);
    cudaGetSymbolAddress((void**)&khi, g_khi);
    cudaGetSymbolAddress((void**)&klo, g_klo);
    cudaGetSymbolAddress((void**)&vhi, g_vhi);
    cudaGetSymbolAddress((void**)&vlo, g_vlo);

    const int smem_qkv = 3 * (128 * 128 + 128 * 128);   // 98304
    const int smem_prj = 3 * (64 * 128 + 128 * 128);    // 73728
    cudaFuncSetAttribute(mma_gemm<128, 1>,
                         cudaFuncAttributeMaxDynamicSharedMemorySize, smem_qkv);
    cudaFuncSetAttribute(mma_gemm<64, 0>,
                         cudaFuncAttributeMaxDynamicSharedMemorySize, smem_prj);
    cudaFuncSetAttribute(attn_mma,
                         cudaFuncAttributeMaxDynamicSharedMemorySize, AT_SMEM);

    // Fused prologue: split x, split W, segment starts
    int n4 = N * D / 4;
    int total = n4 + 4 * WELEM / 4 + N;
    prep_kernel<<<(total + 255) / 256, 256>>>(x, Wq, Wk, Wv, Wp, batch, N);

    // Fused QKV: grid.y 0-3 -> Wq, 4-7 -> Wk, 8-11 -> Wv
    mma_gemm<128, 1><<<dim3((N + 127) / 128, 12), 256, smem_qkv>>>(
        ahi, alo, whi, wlo, WELEM, bq, bk, bv, nullptr,
        qhi, qlo, khi, klo, vhi, vlo, nullptr, N);

    attn_mma<<<NB * NHEAD, 256, AT_SMEM>>>(attn_bias);

    // Output projection + bias + residual (W plane 3)
    mma_gemm<64, 0><<<dim3((N + 63) / 64, 4), 256, smem_prj>>>(
        ahi, alo, whi + 3 * WELEM, wlo + 3 * WELEM, 0,
        bp, bp, bp, yp,
        nullptr, nullptr, nullptr, nullptr, nullptr, nullptr, x, N);

    ln_kernel<<<N, 256>>>(ln_w, ln_b, out);
}

// round 16
// speedup vs baseline: 1.3863x; 1.0002x over previous
#include <cuda_runtime.h>
#include <cuda_fp16.h>
#include <math.h>
#include <stdint.h>

// Problem constants
#define D     512
#define NHEAD 16
#define HS    32
#define NB    64
#define MAXN  128
#define ATT_SCALE 0.17677669529663687f
#define LN_EPS 1e-5f
#define MAX_ROWS 8192
#define WELEM (512 * 512)

// Scratch
__device__ float g_y[MAX_ROWS * D];
__device__ int   g_starts[NB + 1];
__device__ __half g_whi[4 * WELEM];
__device__ __half g_wlo[4 * WELEM];
__device__ __half g_ahi[MAX_ROWS * D];
__device__ __half g_alo[MAX_ROWS * D];
__device__ __half g_qhi[MAX_ROWS * D];
__device__ __half g_qlo[MAX_ROWS * D];
__device__ __half g_khi[MAX_ROWS * D];
__device__ __half g_klo[MAX_ROWS * D];
__device__ __half g_vhi[MAX_ROWS * D];
__device__ __half g_vlo[MAX_ROWS * D];

#define SWZ128(o) ((o) ^ (((o) >> 3) & 0x70u))
#define SWZ256(o) ((o) ^ (((o) >> 4) & 0x70u))

__device__ __forceinline__ uint32_t smem_to_u32(const void* p) {
    uint32_t a;
    asm("{ .reg .u64 t; cvta.to.shared.u64 t, %1; cvt.u32.u64 %0, t; }"
        : "=r"(a) : "l"(p));
    return a;
}
__device__ __forceinline__ void ldsm4(uint32_t* r, uint32_t addr) {
    asm volatile("ldmatrix.sync.aligned.m8n8.x4.shared.b16 {%0,%1,%2,%3}, [%4];"
                 : "=r"(r[0]), "=r"(r[1]), "=r"(r[2]), "=r"(r[3]) : "r"(addr));
}
// non-volatile: register-only op, ptxas may schedule freely
__device__ __forceinline__ void mma16816(float* c, const uint32_t* a,
                                         const uint32_t* b) {
    asm("mma.sync.aligned.m16n8k16.row.col.f32.f16.f16.f32 "
        "{%0,%1,%2,%3}, {%4,%5,%6,%7}, {%8,%9}, {%0,%1,%2,%3};"
        : "+f"(c[0]), "+f"(c[1]), "+f"(c[2]), "+f"(c[3])
        : "r"(a[0]), "r"(a[1]), "r"(a[2]), "r"(a[3]), "r"(b[0]), "r"(b[1]));
}
__device__ __forceinline__ uint32_t packh(__half a, __half b) {
    __half2 h = __halves2half2(a, b);
    return *reinterpret_cast<uint32_t*>(&h);
}
__device__ __forceinline__ void split2(float x, __half& hi, __half& lo) {
    hi = __float2half_rn(x);
    lo = __float2half_rn(x - __half2float(hi));
}
__device__ __forceinline__ void cp_async16(uint32_t dst, const void* src, int sz) {
    asm volatile("cp.async.cg.shared.global [%0], [%1], 16, %2;"
                 :: "r"(dst), "l"(src), "r"(sz) : "memory");
}
#define CP_COMMIT() asm volatile("cp.async.commit_group;" ::: "memory")
#define CP_WAIT(n)  asm volatile("cp.async.wait_group %0;" :: "n"(n) : "memory")

// ---------------------------------------------------------------------------
// Fused prologue: starts + W split + x split, one launch.
// ---------------------------------------------------------------------------
__global__ void prep_kernel(const float* __restrict__ x,
                            const float* __restrict__ Wq,
                            const float* __restrict__ Wk,
                            const float* __restrict__ Wv,
                            const float* __restrict__ Wp,
                            const int* __restrict__ batch, int N) {
    int n4 = N * D / 4;
    const int w4 = 4 * WELEM / 4;
    int i = blockIdx.x * blockDim.x + threadIdx.x;
    if (i < n4) {
        float4 v = reinterpret_cast<const float4*>(x)[i];
        __half hx, hy, hz, hw, lx, ly, lz, lw;
        split2(v.x, hx, lx); split2(v.y, hy, ly);
        split2(v.z, hz, lz); split2(v.w, hw, lw);
        uint2 hi, lo;
        hi.x = packh(hx, hy); hi.y = packh(hz, hw);
        lo.x = packh(lx, ly); lo.y = packh(lz, lw);
        reinterpret_cast<uint2*>(g_ahi)[i] = hi;
        reinterpret_cast<uint2*>(g_alo)[i] = lo;
    } else if (i < n4 + w4) {
        int j = i - n4;
        int j4 = j * 4;
        int w = j4 >> 18;
        int off = j4 & (WELEM - 1);
        const float* src = (w == 0) ? Wq : (w == 1) ? Wk : (w == 2) ? Wv : Wp;
        float4 v = *reinterpret_cast<const float4*>(&src[off]);
        __half hx, hy, hz, hw, lx, ly, lz, lw;
        split2(v.x, hx, lx); split2(v.y, hy, ly);
        split2(v.z, hz, lz); split2(v.w, hw, lw);
        uint2 hi, lo;
        hi.x = packh(hx, hy); hi.y = packh(hz, hw);
        lo.x = packh(lx, ly); lo.y = packh(lz, lw);
        reinterpret_cast<uint2*>(g_whi)[j] = hi;
        reinterpret_cast<uint2*>(g_wlo)[j] = lo;
    } else if (i < n4 + w4 + N) {
        int j = i - n4 - w4;
        int b = batch[j];
        if (j == 0 || batch[j - 1] != b) g_starts[b] = j;
        if (j == N - 1) g_starts[NB] = N;
    }
}

// ---------------------------------------------------------------------------
// split-fp16 2-term mma.sync GEMM: (Ahi+Alo) x Whi  (W-lo dropped; ~2.4e-4
// rel error per GEMM, calibrated against the 3-term baseline).
// Block tile BM x 128, 256 thr = 8 warps (4m x 2n), 2 CTAs/SM, cp.async x3.
// ---------------------------------------------------------------------------
#define GBK 32
#define NSTAGE (D / GBK)

template <int BM, int HOUT>
__global__ void __launch_bounds__(256, 2)
mma_gemm(const __half* __restrict__ Ahi, const __half* __restrict__ Alo,
         const __half* __restrict__ Whi, const __half* __restrict__ Wlo,
         int wstride,
         const float* __restrict__ b0, const float* __restrict__ b1,
         const float* __restrict__ b2,
         float* __restrict__ o0,
         __half* __restrict__ oh0, __half* __restrict__ ol0,
         __half* __restrict__ oh1, __half* __restrict__ ol1,
         __half* __restrict__ oh2, __half* __restrict__ ol2,
         const float* __restrict__ resid, int M) {
    constexpr int MF = BM / 64;
    constexpr int ABYTES = BM * 128;
    constexpr int BBYTES = 128 * 128;
    constexpr int BUF = ABYTES + BBYTES;
    constexpr int A_ITER = (ABYTES / 16) / 256;
    constexpr int B_ITER = (BBYTES / 16) / 256;
    extern __shared__ __align__(128) char smem[];
    uint32_t sbase = smem_to_u32(smem);
    int tid = threadIdx.x;
    int lane = tid & 31;
    int wid = tid >> 5;
    int warp_m = wid & 3;
    int warp_n = wid >> 2;
    int bm = blockIdx.x * BM;
    int ntile = blockIdx.y;
    int wsel = ntile >> 2;
    const __half* WH = Whi + (size_t)wsel * wstride;
    const __half* WL = Wlo + (size_t)wsel * wstride;
    const float* bias = (wsel == 0) ? b0 : (wsel == 1 ? b1 : b2);
    __half* OutHi = (wsel == 0) ? oh0 : (wsel == 1 ? oh1 : oh2);
    __half* OutLo = (wsel == 0) ? ol0 : (wsel == 1 ? ol1 : ol2);
    int nbase = (ntile & 3) * 128;

    auto stage = [&](int s, int d) {
        int k0 = s * GBK;
        uint32_t base = sbase + d * BUF;
#pragma unroll
        for (int j = 0; j < A_ITER; j++) {
            int c = tid + j * 256;
            int row = c >> 3, sub = c & 7, plane = sub >> 2, i = sub & 3;
            uint32_t dst = base + SWZ128((uint32_t)(row * 128 + plane * 64 + i * 16));
            const __half* sp = plane ? Alo : Ahi;
            int gr = bm + row;
            const __half* src = sp + (size_t)gr * D + k0 + i * 8;
            cp_async16(dst, src, gr < M ? 16 : 0);
        }
#pragma unroll
        for (int j = 0; j < B_ITER; j++) {
            int c = tid + j * 256;
            int row = c >> 3, sub = c & 7, plane = sub >> 2, i = sub & 3;
            uint32_t dst = base + ABYTES +
                           SWZ128((uint32_t)(row * 128 + plane * 64 + i * 16));
            const __half* sp = plane ? WL : WH;
            const __half* src = sp + (size_t)(nbase + row) * D + k0 + i * 8;
            cp_async16(dst, src, 16);
        }
        CP_COMMIT();
    };

    float acc[MF][8][4];
#pragma unroll
    for (int i = 0; i < MF; i++)
#pragma unroll
        for (int j = 0; j < 8; j++)
#pragma unroll
            for (int k = 0; k < 4; k++) acc[i][j][k] = 0.f;

    stage(0, 0);
    stage(1, 1);

    for (int s = 0; s < NSTAGE; s++) {
        if (s == NSTAGE - 1) CP_WAIT(0); else CP_WAIT(1);
        __syncthreads();
        if (s + 2 < NSTAGE) stage(s + 2, (s + 2) % 3);

        uint32_t Abase = sbase + (s % 3) * BUF;
        uint32_t Bbase = Abase + ABYTES;
#pragma unroll
        for (int ks = 0; ks < 2; ks++) {
            uint32_t ah[MF][4], al[MF][4];
#pragma unroll
            for (int mf = 0; mf < MF; mf++) {
                int row = warp_m * (16 * MF) + mf * 16 + (lane & 15);
                uint32_t off =
                    (uint32_t)(row * 128 + ks * 32 + ((lane >> 4) << 4));
                ldsm4(ah[mf], Abase + SWZ128(off));
                ldsm4(al[mf], Abase + SWZ128(off + 64));
            }
#pragma unroll
            for (int np = 0; np < 4; np++) {
                int g = lane >> 3;
                int n = warp_n * 64 + np * 16 + ((g >> 1) << 3) + (lane & 7);
                uint32_t off = (uint32_t)(n * 128 + ks * 32 + ((g & 1) << 4));
                uint32_t rh[4];
                ldsm4(rh, Bbase + SWZ128(off));
#pragma unroll
                for (int mf = 0; mf < MF; mf++) {
                    mma16816(acc[mf][np * 2], ah[mf], rh);
                    mma16816(acc[mf][np * 2 + 1], ah[mf], rh + 2);
                    mma16816(acc[mf][np * 2], al[mf], rh);
                    mma16816(acc[mf][np * 2 + 1], al[mf], rh + 2);
                }
            }
        }
    }

    // ---- epilogue
#pragma unroll
    for (int mf = 0; mf < MF; mf++) {
#pragma unroll
        for (int nf = 0; nf < 8; nf++) {
            int gc = nbase + warp_n * 64 + nf * 8 + (lane & 3) * 2;
            float2 bb = *reinterpret_cast<const float2*>(&bias[gc]);
            int r0 = bm + warp_m * (16 * MF) + mf * 16 + (lane >> 2);
#pragma unroll
            for (int hh = 0; hh < 2; hh++) {
                int gr = r0 + hh * 8;
                if (gr >= M) continue;
                float vx = acc[mf][nf][hh * 2 + 0] + bb.x;
                float vy = acc[mf][nf][hh * 2 + 1] + bb.y;
                if (HOUT) {
                    __half hx, hy, lx, ly;
                    split2(vx, hx, lx); split2(vy, hy, ly);
                    *reinterpret_cast<uint32_t*>(&OutHi[(size_t)gr * D + gc]) =
                        packh(hx, hy);
                    *reinterpret_cast<uint32_t*>(&OutLo[(size_t)gr * D + gc]) =
                        packh(lx, ly);
                } else {
                    if (resid) {
                        float2 rr = *reinterpret_cast<const float2*>(
                            &resid[(size_t)gr * D + gc]);
                        vx += rr.x; vy += rr.y;
                    }
                    float2 v; v.x = vx; v.y = vy;
                    *reinterpret_cast<float2*>(&o0[(size_t)gr * D + gc]) = v;
                }
            }
        }
    }
}

// ---------------------------------------------------------------------------
// mma attention (R13-proven 3-term): one block per (b,h), 8 warps, 2 CTAs/SM.
// ---------------------------------------------------------------------------
#define AT_PHI   0
#define AT_PLO   32768
#define AT_Q     0
#define AT_K     16384
#define AT_VTHI  65536
#define AT_VTLO  73728
#define AT_PMAX  81920
#define AT_PSUM  83968
#define AT_LINV  86016
#define AT_SMEM  86528

__global__ void __launch_bounds__(256, 2)
attn_mma(const float* __restrict__ attn_bias) {
    extern __shared__ __align__(128) char sm[];
    uint32_t sb = smem_to_u32(sm);
    int tid = threadIdx.x;
    int lane = tid & 31;
    int wid = tid >> 5;
    int bh = blockIdx.x;
    int b = bh >> 4;
    int h = bh & 15;
    int s0 = g_starts[b];
    int n = g_starts[b + 1] - s0;

    {
        int row = tid >> 1;
        int part = tid & 1;
        const __half* qp = part ? g_qlo : g_qhi;
        const __half* kp = part ? g_klo : g_khi;
        size_t src = (size_t)(s0 + row) * D + h * HS;
#pragma unroll
        for (int i = 0; i < 4; i++) {
            uint4 qv = make_uint4(0, 0, 0, 0), kv = make_uint4(0, 0, 0, 0);
            if (row < n) {
                qv = *reinterpret_cast<const uint4*>(&qp[src + i * 8]);
                kv = *reinterpret_cast<const uint4*>(&kp[src + i * 8]);
            }
            uint32_t off = SWZ128((uint32_t)(row * 128 + part * 64 + i * 16));
            *reinterpret_cast<uint4*>(sm + AT_Q + off) = qv;
            *reinterpret_cast<uint4*>(sm + AT_K + off) = kv;
        }
    }
    {
        int j = tid >> 1;
        int part = tid & 1;
        size_t src = (size_t)(s0 + j) * D + h * HS + part * 16;
#pragma unroll
        for (int rep = 0; rep < 2; rep++) {
            uint4 hv = make_uint4(0, 0, 0, 0), lv = make_uint4(0, 0, 0, 0);
            if (j < n) {
                hv = *reinterpret_cast<const uint4*>(&g_vhi[src + rep * 8]);
                lv = *reinterpret_cast<const uint4*>(&g_vlo[src + rep * 8]);
            }
            const __half* hp = reinterpret_cast<const __half*>(&hv);
            const __half* lp = reinterpret_cast<const __half*>(&lv);
#pragma unroll
            for (int i = 0; i < 8; i++) {
                int d = part * 16 + rep * 8 + i;
                uint32_t off = SWZ256((uint32_t)(d * 256 + j * 2));
                *reinterpret_cast<__half*>(sm + AT_VTHI + off) = hp[i];
                *reinterpret_cast<__half*>(sm + AT_VTLO + off) = lp[i];
            }
        }
    }
    __syncthreads();

    int warp_m = wid & 1;
    int warp_n = wid >> 1;
    float sc[4][4][4];
#pragma unroll
    for (int i = 0; i < 4; i++)
#pragma unroll
        for (int j = 0; j < 4; j++)
#pragma unroll
            for (int k = 0; k < 4; k++) sc[i][j][k] = 0.f;

#pragma unroll
    for (int ks = 0; ks < 2; ks++) {
        uint32_t ah[4][4], al[4][4];
#pragma unroll
        for (int mf = 0; mf < 4; mf++) {
            int row = warp_m * 64 + mf * 16 + (lane & 15);
            uint32_t off = (uint32_t)(row * 128 + ks * 32 + ((lane >> 4) << 4));
            ldsm4(ah[mf], sb + AT_Q + SWZ128(off));
            ldsm4(al[mf], sb + AT_Q + SWZ128(off + 64));
        }
        uint32_t bh2[4][2], bl2[4][2];
#pragma unroll
        for (int np = 0; np < 2; np++) {
            int g = lane >> 3;
            int nn = warp_n * 32 + np * 16 + ((g >> 1) << 3) + (lane & 7);
            uint32_t off = (uint32_t)(nn * 128 + ks * 32 + ((g & 1) << 4));
            uint32_t r[4];
            ldsm4(r, sb + AT_K + SWZ128(off));
            bh2[np * 2][0] = r[0]; bh2[np * 2][1] = r[1];
            bh2[np * 2 + 1][0] = r[2]; bh2[np * 2 + 1][1] = r[3];
            ldsm4(r, sb + AT_K + SWZ128(off + 64));
            bl2[np * 2][0] = r[0]; bl2[np * 2][1] = r[1];
            bl2[np * 2 + 1][0] = r[2]; bl2[np * 2 + 1][1] = r[3];
        }
#pragma unroll
        for (int mf = 0; mf < 4; mf++)
#pragma unroll
            for (int nf = 0; nf < 4; nf++) {
                mma16816(sc[mf][nf], ah[mf], bh2[nf]);
                mma16816(sc[mf][nf], ah[mf], bl2[nf]);
                mma16816(sc[mf][nf], al[mf], bh2[nf]);
            }
    }

    const float* bb = attn_bias + ((size_t)(b * NHEAD + h)) * MAXN * MAXN;
#pragma unroll
    for (int mf = 0; mf < 4; mf++) {
        int r0 = warp_m * 64 + mf * 16 + (lane >> 2);
#pragma unroll
        for (int nf = 0; nf < 4; nf++) {
            int c0 = warp_n * 32 + nf * 8 + (lane & 3) * 2;
#pragma unroll
            for (int hh = 0; hh < 2; hh++) {
                int r = r0 + hh * 8;
                float2 bv = *reinterpret_cast<const float2*>(&bb[r * MAXN + c0]);
                float v0 = sc[mf][nf][hh * 2] * ATT_SCALE + bv.x;
                float v1 = sc[mf][nf][hh * 2 + 1] * ATT_SCALE + bv.y;
                if (c0 >= n) v0 = -1e30f;
                if (c0 + 1 >= n) v1 = -1e30f;
                sc[mf][nf][hh * 2] = v0;
                sc[mf][nf][hh * 2 + 1] = v1;
            }
        }
    }

#pragma unroll
    for (int mf = 0; mf < 4; mf++)
#pragma unroll
        for (int hh = 0; hh < 2; hh++) {
            float mx = -1e30f;
#pragma unroll
            for (int nf = 0; nf < 4; nf++)
                mx = fmaxf(mx, fmaxf(sc[mf][nf][hh * 2], sc[mf][nf][hh * 2 + 1]));
            mx = fmaxf(mx, __shfl_xor_sync(0xffffffffu, mx, 1));
            mx = fmaxf(mx, __shfl_xor_sync(0xffffffffu, mx, 2));
            int row = warp_m * 64 + mf * 16 + (lane >> 2) + hh * 8;
            if ((lane & 3) == 0)
                *reinterpret_cast<float*>(sm + AT_PMAX + (row * 4 + warp_n) * 4) = mx;
        }
    __syncthreads();

#pragma unroll
    for (int mf = 0; mf < 4; mf++)
#pragma unroll
        for (int hh = 0; hh < 2; hh++) {
            int row = warp_m * 64 + mf * 16 + (lane >> 2) + hh * 8;
            float4 m4 = *reinterpret_cast<float4*>(sm + AT_PMAX + row * 16);
            float m = fmaxf(fmaxf(m4.x, m4.y), fmaxf(m4.z, m4.w));
            float ssum = 0.f;
#pragma unroll
            for (int nf = 0; nf < 4; nf++) {
                float p0 = __expf(sc[mf][nf][hh * 2] - m);
                float p1 = __expf(sc[mf][nf][hh * 2 + 1] - m);
                ssum += p0 + p1;
                int c0 = warp_n * 32 + nf * 8 + (lane & 3) * 2;
                __half h0, h1, l0, l1;
                split2(p0, h0, l0); split2(p1, h1, l1);
                uint32_t off = (uint32_t)(row * 256 + c0 * 2);
                *reinterpret_cast<uint32_t*>(sm + AT_PHI + SWZ256(off)) = packh(h0, h1);
                *reinterpret_cast<uint32_t*>(sm + AT_PLO + SWZ256(off)) = packh(l0, l1);
            }
            ssum += __shfl_xor_sync(0xffffffffu, ssum, 1);
            ssum += __shfl_xor_sync(0xffffffffu, ssum, 2);
            if ((lane & 3) == 0)
                *reinterpret_cast<float*>(sm + AT_PSUM + (row * 4 + warp_n) * 4) = ssum;
        }
    __syncthreads();

    if (tid < 128) {
        float4 s4 = *reinterpret_cast<float4*>(sm + AT_PSUM + tid * 16);
        float l = s4.x + s4.y + s4.z + s4.w;
        *reinterpret_cast<float*>(sm + AT_LINV + tid * 4) = 1.f / l;
    }
    __syncthreads();

    float oc[4][4];
#pragma unroll
    for (int j = 0; j < 4; j++)
#pragma unroll
        for (int k = 0; k < 4; k++) oc[j][k] = 0.f;

#pragma unroll
    for (int ks = 0; ks < 8; ks++) {
        uint32_t ph[4], pl[4];
        {
            int row = wid * 16 + (lane & 15);
            uint32_t off = (uint32_t)(row * 256 + ks * 32 + ((lane >> 4) << 4));
            ldsm4(ph, sb + AT_PHI + SWZ256(off));
            ldsm4(pl, sb + AT_PLO + SWZ256(off));
        }
        uint32_t vh[4][2], vl[4][2];
#pragma unroll
        for (int np = 0; np < 2; np++) {
            int g = lane >> 3;
            int nn = np * 16 + ((g >> 1) << 3) + (lane & 7);
            uint32_t off = (uint32_t)(nn * 256 + ks * 32 + ((g & 1) << 4));
            uint32_t r[4];
            ldsm4(r, sb + AT_VTHI + SWZ256(off));
            vh[np * 2][0] = r[0]; vh[np * 2][1] = r[1];
            vh[np * 2 + 1][0] = r[2]; vh[np * 2 + 1][1] = r[3];
            ldsm4(r, sb + AT_VTLO + SWZ256(off));
            vl[np * 2][0] = r[0]; vl[np * 2][1] = r[1];
            vl[np * 2 + 1][0] = r[2]; vl[np * 2 + 1][1] = r[3];
        }
#pragma unroll
        for (int nf = 0; nf < 4; nf++) {
            mma16816(oc[nf], ph, vh[nf]);
            mma16816(oc[nf], ph, vl[nf]);
            mma16816(oc[nf], pl, vh[nf]);
        }
    }

    int r0 = wid * 16 + (lane >> 2);
#pragma unroll
    for (int hh = 0; hh < 2; hh++) {
        int row = r0 + hh * 8;
        if (row >= n) continue;
        float linv = *reinterpret_cast<float*>(sm + AT_LINV + row * 4);
        size_t base = (size_t)(s0 + row) * D + h * HS;
#pragma unroll
        for (int nf = 0; nf < 4; nf++) {
            int d0 = nf * 8 + (lane & 3) * 2;
            float o0 = oc[nf][hh * 2] * linv;
            float o1 = oc[nf][hh * 2 + 1] * linv;
            __half h0, h1, l0, l1;
            split2(o0, h0, l0); split2(o1, h1, l1);
            *reinterpret_cast<uint32_t*>(&g_ahi[base + d0]) = packh(h0, h1);
            *reinterpret_cast<uint32_t*>(&g_alo[base + d0]) = packh(l0, l1);
        }
    }
}

// ---------------------------------------------------------------------------
// LayerNorm
// ---------------------------------------------------------------------------
__global__ void __launch_bounds__(256)
ln_kernel(const float* __restrict__ ln_w, const float* __restrict__ ln_b,
          float* __restrict__ out) {
    int row = blockIdx.x;
    const float* y = g_y + (size_t)row * D;
    int tid = threadIdx.x;

    float v0 = y[tid];
    float v1 = y[tid + 256];
    float s = v0 + v1;
    float q = v0 * v0 + v1 * v1;
#pragma unroll
    for (int off = 16; off; off >>= 1) {
        s += __shfl_down_sync(0xffffffffu, s, off);
        q += __shfl_down_sync(0xffffffffu, q, off);
    }
    __shared__ float rs[8], rq[8];
    __shared__ float s_mu, s_rstd;
    if ((tid & 31) == 0) { rs[tid >> 5] = s; rq[tid >> 5] = q; }
    __syncthreads();
    if (tid == 0) {
        float S = 0.f, Q = 0.f;
#pragma unroll
        for (int i = 0; i < 8; i++) { S += rs[i]; Q += rq[i]; }
        float mu = S * (1.f / D);
        float var = Q * (1.f / D) - mu * mu;
        s_mu = mu;
        s_rstd = rsqrtf(var + LN_EPS);
    }
    __syncthreads();
    float mu = s_mu, r = s_rstd;
    out[(size_t)row * D + tid] = (v0 - mu) * r * ln_w[tid] + ln_b[tid];
    out[(size_t)row * D + tid + 256] =
        (v1 - mu) * r * ln_w[tid + 256] + ln_b[tid + 256];
}

// ---------------------------------------------------------------------------
extern "C" void kernel_launch(void* const* d_in, const int* in_sizes, int n_in,
                              void* d_out, int out_size) {
    const float* x         = (const float*)d_in[0];
    const float* attn_bias = (const float*)d_in[1];
    const float* Wq = (const float*)d_in[2];
    const float* bq = (const float*)d_in[3];
    const float* Wk = (const float*)d_in[4];
    const float* bk = (const float*)d_in[5];
    const float* Wv = (const float*)d_in[6];
    const float* bv = (const float*)d_in[7];
    const float* Wp = (const float*)d_in[8];
    const float* bp = (const float*)d_in[9];
    const float* ln_w = (const float*)d_in[10];
    const float* ln_b = (const float*)d_in[11];
    const int*   batch = (const int*)d_in[12];

    int N = in_sizes[12];
    float* out = (float*)d_out;

    float *yp;
    __half *whi, *wlo, *ahi, *alo, *qhi, *qlo, *khi, *klo, *vhi, *vlo;
    cudaGetSymbolAddress((void**)&yp, g_y);
    cudaGetSymbolAddress((void**)&whi, g_whi);
    cudaGetSymbolAddress((void**)&wlo, g_wlo);
    cudaGetSymbolAddress((void**)&ahi, g_ahi);
    cudaGetSymbolAddress((void**)&alo, g_alo);
    cudaGetSymbolAddress((void**)&qhi, g_qhi);
    cudaGetSymbolAddress((void**)&qlo, g_qlo);
    cudaGetSymbolAddress((void**)&khi, g_khi);
    cudaGetSymbolAddress((void**)&klo, g_klo);
    cudaGetSymbolAddress((void**)&vhi, g_vhi);
    cudaGetSymbolAddress((void**)&vlo, g_vlo);

    const int smem_qkv = 3 * (128 * 128 + 128 * 128);   // 98304
    const int smem_prj = 3 * (64 * 128 + 128 * 128);    // 73728
    cudaFuncSetAttribute(mma_gemm<128, 1>,
                         cudaFuncAttributeMaxDynamicSharedMemorySize, smem_qkv);
    cudaFuncSetAttribute(mma_gemm<64, 0>,
                         cudaFuncAttributeMaxDynamicSharedMemorySize, smem_prj);
    cudaFuncSetAttribute(attn_mma,
                         cudaFuncAttributeMaxDynamicSharedMemorySize, AT_SMEM);

    // Fused prologue: split x, split W, segment starts
    int n4 = N * D / 4;
    int total = n4 + 4 * WELEM / 4 + N;
    prep_kernel<<<(total + 255) / 256, 256>>>(x, Wq, Wk, Wv, Wp, batch, N);

    // Fused QKV: grid.y 0-3 -> Wq, 4-7 -> Wk, 8-11 -> Wv
    mma_gemm<128, 1><<<dim3((N + 127) / 128, 12), 256, smem_qkv>>>(
        ahi, alo, whi, wlo, WELEM, bq, bk, bv, nullptr,
        qhi, qlo, khi, klo, vhi, vlo, nullptr, N);

    attn_mma<<<NB * NHEAD, 256, AT_SMEM>>>(attn_bias);

    // Output projection + bias + residual (W plane 3)
    mma_gemm<64, 0><<<dim3((N + 63) / 64, 4), 256, smem_prj>>>(
        ahi, alo, whi + 3 * WELEM, wlo + 3 * WELEM, 0,
        bp, bp, bp, yp,
        nullptr, nullptr, nullptr, nullptr, nullptr, nullptr, x, N);

    ln_kernel<<<N, 256>>>(ln_w, ln_b, out);
}

// round 17
// speedup vs baseline: 1.7702x; 1.2769x over previous
#include <cuda_runtime.h>
#include <cuda_fp16.h>
#include <math.h>
#include <stdint.h>

// Problem constants
#define D     512
#define NHEAD 16
#define HS    32
#define NB    64
#define MAXN  128
#define ATT_SCALE 0.17677669529663687f
#define LN_EPS 1e-5f
#define MAX_ROWS 8192
#define WELEM (512 * 512)

// Scratch
__device__ float g_y[MAX_ROWS * D];
__device__ int   g_starts[NB + 1];
__device__ __half g_whi[4 * WELEM];
__device__ __half g_wlo[4 * WELEM];
__device__ __half g_ahi[MAX_ROWS * D];
__device__ __half g_alo[MAX_ROWS * D];
__device__ __half g_qhi[MAX_ROWS * D];
__device__ __half g_qlo[MAX_ROWS * D];
__device__ __half g_khi[MAX_ROWS * D];
__device__ __half g_klo[MAX_ROWS * D];
__device__ __half g_vhi[MAX_ROWS * D];
__device__ __half g_vlo[MAX_ROWS * D];

#define SWZ128(o) ((o) ^ (((o) >> 3) & 0x70u))
#define SWZ256(o) ((o) ^ (((o) >> 4) & 0x70u))

__device__ __forceinline__ uint32_t smem_to_u32(const void* p) {
    uint32_t a;
    asm("{ .reg .u64 t; cvta.to.shared.u64 t, %1; cvt.u32.u64 %0, t; }"
        : "=r"(a) : "l"(p));
    return a;
}
__device__ __forceinline__ void ldsm4(uint32_t* r, uint32_t addr) {
    asm volatile("ldmatrix.sync.aligned.m8n8.x4.shared.b16 {%0,%1,%2,%3}, [%4];"
                 : "=r"(r[0]), "=r"(r[1]), "=r"(r[2]), "=r"(r[3]) : "r"(addr));
}
// non-volatile: register-only op, ptxas may schedule freely
__device__ __forceinline__ void mma16816(float* c, const uint32_t* a,
                                         const uint32_t* b) {
    asm("mma.sync.aligned.m16n8k16.row.col.f32.f16.f16.f32 "
        "{%0,%1,%2,%3}, {%4,%5,%6,%7}, {%8,%9}, {%0,%1,%2,%3};"
        : "+f"(c[0]), "+f"(c[1]), "+f"(c[2]), "+f"(c[3])
        : "r"(a[0]), "r"(a[1]), "r"(a[2]), "r"(a[3]), "r"(b[0]), "r"(b[1]));
}
__device__ __forceinline__ uint32_t packh(__half a, __half b) {
    __half2 h = __halves2half2(a, b);
    return *reinterpret_cast<uint32_t*>(&h);
}
__device__ __forceinline__ void split2(float x, __half& hi, __half& lo) {
    hi = __float2half_rn(x);
    lo = __float2half_rn(x - __half2float(hi));
}
__device__ __forceinline__ void cp_async16(uint32_t dst, const void* src, int sz) {
    asm volatile("cp.async.cg.shared.global [%0], [%1], 16, %2;"
                 :: "r"(dst), "l"(src), "r"(sz) : "memory");
}
#define CP_COMMIT() asm volatile("cp.async.commit_group;" ::: "memory")
#define CP_WAIT(n)  asm volatile("cp.async.wait_group %0;" :: "n"(n) : "memory")

// ---------------------------------------------------------------------------
// Fused prologue: starts + W split + x split, one launch.
// ---------------------------------------------------------------------------
__global__ void prep_kernel(const float* __restrict__ x,
                            const float* __restrict__ Wq,
                            const float* __restrict__ Wk,
                            const float* __restrict__ Wv,
                            const float* __restrict__ Wp,
                            const int* __restrict__ batch, int N) {
    int n4 = N * D / 4;
    const int w4 = 4 * WELEM / 4;
    int i = blockIdx.x * blockDim.x + threadIdx.x;
    if (i < n4) {
        float4 v = reinterpret_cast<const float4*>(x)[i];
        __half hx, hy, hz, hw, lx, ly, lz, lw;
        split2(v.x, hx, lx); split2(v.y, hy, ly);
        split2(v.z, hz, lz); split2(v.w, hw, lw);
        uint2 hi, lo;
        hi.x = packh(hx, hy); hi.y = packh(hz, hw);
        lo.x = packh(lx, ly); lo.y = packh(lz, lw);
        reinterpret_cast<uint2*>(g_ahi)[i] = hi;
        reinterpret_cast<uint2*>(g_alo)[i] = lo;
    } else if (i < n4 + w4) {
        int j = i - n4;
        int j4 = j * 4;
        int w = j4 >> 18;
        int off = j4 & (WELEM - 1);
        const float* src = (w == 0) ? Wq : (w == 1) ? Wk : (w == 2) ? Wv : Wp;
        float4 v = *reinterpret_cast<const float4*>(&src[off]);
        __half hx, hy, hz, hw, lx, ly, lz, lw;
        split2(v.x, hx, lx); split2(v.y, hy, ly);
        split2(v.z, hz, lz); split2(v.w, hw, lw);
        uint2 hi, lo;
        hi.x = packh(hx, hy); hi.y = packh(hz, hw);
        lo.x = packh(lx, ly); lo.y = packh(lz, lw);
        reinterpret_cast<uint2*>(g_whi)[j] = hi;
        reinterpret_cast<uint2*>(g_wlo)[j] = lo;
    } else if (i < n4 + w4 + N) {
        int j = i - n4 - w4;
        int b = batch[j];
        if (j == 0 || batch[j - 1] != b) g_starts[b] = j;
        if (j == N - 1) g_starts[NB] = N;
    }
}

// ---------------------------------------------------------------------------
// fp16 single-term mma.sync GEMM: Ahi x Whi (both lo planes dropped;
// each dropped plane measured at ~1.2e-5 rel error -> total ~2.5e-5).
// Block tile BM x 128, 256 thr = 8 warps (4m x 2n), 2 CTAs/SM, cp.async x3.
// Smem layout keeps 128B rows (lo halves unwritten) so swizzle is unchanged.
// ---------------------------------------------------------------------------
#define GBK 32
#define NSTAGE (D / GBK)

template <int BM, int HOUT>
__global__ void __launch_bounds__(256, 2)
mma_gemm(const __half* __restrict__ Ahi,
         const __half* __restrict__ Whi,
         int wstride,
         const float* __restrict__ b0, const float* __restrict__ b1,
         const float* __restrict__ b2,
         float* __restrict__ o0,
         __half* __restrict__ oh0, __half* __restrict__ ol0,
         __half* __restrict__ oh1, __half* __restrict__ ol1,
         __half* __restrict__ oh2, __half* __restrict__ ol2,
         const float* __restrict__ resid, int M) {
    constexpr int MF = BM / 64;
    constexpr int ABYTES = BM * 128;
    constexpr int BBYTES = 128 * 128;
    constexpr int BUF = ABYTES + BBYTES;
    constexpr int A_ITER = (BM * 4) / 256;   // 16B hi-chunks per thread
    extern __shared__ __align__(128) char smem[];
    uint32_t sbase = smem_to_u32(smem);
    int tid = threadIdx.x;
    int lane = tid & 31;
    int wid = tid >> 5;
    int warp_m = wid & 3;
    int warp_n = wid >> 2;
    int bm = blockIdx.x * BM;
    int ntile = blockIdx.y;
    int wsel = ntile >> 2;
    const __half* WH = Whi + (size_t)wsel * wstride;
    const float* bias = (wsel == 0) ? b0 : (wsel == 1 ? b1 : b2);
    __half* OutHi = (wsel == 0) ? oh0 : (wsel == 1 ? oh1 : oh2);
    __half* OutLo = (wsel == 0) ? ol0 : (wsel == 1 ? ol1 : ol2);
    int nbase = (ntile & 3) * 128;

    auto stage = [&](int s, int d) {
        int k0 = s * GBK;
        uint32_t base = sbase + d * BUF;
        // A hi half only: BM rows x 64B
#pragma unroll
        for (int j = 0; j < A_ITER; j++) {
            int c = tid + j * 256;
            int row = c >> 2, i = c & 3;
            uint32_t dst = base + SWZ128((uint32_t)(row * 128 + i * 16));
            int gr = bm + row;
            const __half* src = Ahi + (size_t)gr * D + k0 + i * 8;
            cp_async16(dst, src, gr < M ? 16 : 0);
        }
        // B hi half only: 128 rows x 64B
#pragma unroll
        for (int j = 0; j < 2; j++) {
            int c = tid + j * 256;
            int row = c >> 2, i = c & 3;
            uint32_t dst = base + ABYTES +
                           SWZ128((uint32_t)(row * 128 + i * 16));
            const __half* src = WH + (size_t)(nbase + row) * D + k0 + i * 8;
            cp_async16(dst, src, 16);
        }
        CP_COMMIT();
    };

    float acc[MF][8][4];
#pragma unroll
    for (int i = 0; i < MF; i++)
#pragma unroll
        for (int j = 0; j < 8; j++)
#pragma unroll
            for (int k = 0; k < 4; k++) acc[i][j][k] = 0.f;

    stage(0, 0);
    stage(1, 1);

    for (int s = 0; s < NSTAGE; s++) {
        if (s == NSTAGE - 1) CP_WAIT(0); else CP_WAIT(1);
        __syncthreads();
        if (s + 2 < NSTAGE) stage(s + 2, (s + 2) % 3);

        uint32_t Abase = sbase + (s % 3) * BUF;
        uint32_t Bbase = Abase + ABYTES;
#pragma unroll
        for (int ks = 0; ks < 2; ks++) {
            uint32_t ah[MF][4];
#pragma unroll
            for (int mf = 0; mf < MF; mf++) {
                int row = warp_m * (16 * MF) + mf * 16 + (lane & 15);
                uint32_t off =
                    (uint32_t)(row * 128 + ks * 32 + ((lane >> 4) << 4));
                ldsm4(ah[mf], Abase + SWZ128(off));
            }
#pragma unroll
            for (int np = 0; np < 4; np++) {
                int g = lane >> 3;
                int n = warp_n * 64 + np * 16 + ((g >> 1) << 3) + (lane & 7);
                uint32_t off = (uint32_t)(n * 128 + ks * 32 + ((g & 1) << 4));
                uint32_t rh[4];
                ldsm4(rh, Bbase + SWZ128(off));
#pragma unroll
                for (int mf = 0; mf < MF; mf++) {
                    mma16816(acc[mf][np * 2], ah[mf], rh);
                    mma16816(acc[mf][np * 2 + 1], ah[mf], rh + 2);
                }
            }
        }
    }

    // ---- epilogue
#pragma unroll
    for (int mf = 0; mf < MF; mf++) {
#pragma unroll
        for (int nf = 0; nf < 8; nf++) {
            int gc = nbase + warp_n * 64 + nf * 8 + (lane & 3) * 2;
            float2 bb = *reinterpret_cast<const float2*>(&bias[gc]);
            int r0 = bm + warp_m * (16 * MF) + mf * 16 + (lane >> 2);
#pragma unroll
            for (int hh = 0; hh < 2; hh++) {
                int gr = r0 + hh * 8;
                if (gr >= M) continue;
                float vx = acc[mf][nf][hh * 2 + 0] + bb.x;
                float vy = acc[mf][nf][hh * 2 + 1] + bb.y;
                if (HOUT) {
                    __half hx, hy, lx, ly;
                    split2(vx, hx, lx); split2(vy, hy, ly);
                    *reinterpret_cast<uint32_t*>(&OutHi[(size_t)gr * D + gc]) =
                        packh(hx, hy);
                    *reinterpret_cast<uint32_t*>(&OutLo[(size_t)gr * D + gc]) =
                        packh(lx, ly);
                } else {
                    if (resid) {
                        float2 rr = *reinterpret_cast<const float2*>(
                            &resid[(size_t)gr * D + gc]);
                        vx += rr.x; vy += rr.y;
                    }
                    float2 v; v.x = vx; v.y = vy;
                    *reinterpret_cast<float2*>(&o0[(size_t)gr * D + gc]) = v;
                }
            }
        }
    }
}

// ---------------------------------------------------------------------------
// mma attention (R13-proven 3-term): one block per (b,h), 8 warps, 2 CTAs/SM.
// ---------------------------------------------------------------------------
#define AT_PHI   0
#define AT_PLO   32768
#define AT_Q     0
#define AT_K     16384
#define AT_VTHI  65536
#define AT_VTLO  73728
#define AT_PMAX  81920
#define AT_PSUM  83968
#define AT_LINV  86016
#define AT_SMEM  86528

__global__ void __launch_bounds__(256, 2)
attn_mma(const float* __restrict__ attn_bias) {
    extern __shared__ __align__(128) char sm[];
    uint32_t sb = smem_to_u32(sm);
    int tid = threadIdx.x;
    int lane = tid & 31;
    int wid = tid >> 5;
    int bh = blockIdx.x;
    int b = bh >> 4;
    int h = bh & 15;
    int s0 = g_starts[b];
    int n = g_starts[b + 1] - s0;

    {
        int row = tid >> 1;
        int part = tid & 1;
        const __half* qp = part ? g_qlo : g_qhi;
        const __half* kp = part ? g_klo : g_khi;
        size_t src = (size_t)(s0 + row) * D + h * HS;
#pragma unroll
        for (int i = 0; i < 4; i++) {
            uint4 qv = make_uint4(0, 0, 0, 0), kv = make_uint4(0, 0, 0, 0);
            if (row < n) {
                qv = *reinterpret_cast<const uint4*>(&qp[src + i * 8]);
                kv = *reinterpret_cast<const uint4*>(&kp[src + i * 8]);
            }
            uint32_t off = SWZ128((uint32_t)(row * 128 + part * 64 + i * 16));
            *reinterpret_cast<uint4*>(sm + AT_Q + off) = qv;
            *reinterpret_cast<uint4*>(sm + AT_K + off) = kv;
        }
    }
    {
        int j = tid >> 1;
        int part = tid & 1;
        size_t src = (size_t)(s0 + j) * D + h * HS + part * 16;
#pragma unroll
        for (int rep = 0; rep < 2; rep++) {
            uint4 hv = make_uint4(0, 0, 0, 0), lv = make_uint4(0, 0, 0, 0);
            if (j < n) {
                hv = *reinterpret_cast<const uint4*>(&g_vhi[src + rep * 8]);
                lv = *reinterpret_cast<const uint4*>(&g_vlo[src + rep * 8]);
            }
            const __half* hp = reinterpret_cast<const __half*>(&hv);
            const __half* lp = reinterpret_cast<const __half*>(&lv);
#pragma unroll
            for (int i = 0; i < 8; i++) {
                int d = part * 16 + rep * 8 + i;
                uint32_t off = SWZ256((uint32_t)(d * 256 + j * 2));
                *reinterpret_cast<__half*>(sm + AT_VTHI + off) = hp[i];
                *reinterpret_cast<__half*>(sm + AT_VTLO + off) = lp[i];
            }
        }
    }
    __syncthreads();

    int warp_m = wid & 1;
    int warp_n = wid >> 1;
    float sc[4][4][4];
#pragma unroll
    for (int i = 0; i < 4; i++)
#pragma unroll
        for (int j = 0; j < 4; j++)
#pragma unroll
            for (int k = 0; k < 4; k++) sc[i][j][k] = 0.f;

#pragma unroll
    for (int ks = 0; ks < 2; ks++) {
        uint32_t ah[4][4], al[4][4];
#pragma unroll
        for (int mf = 0; mf < 4; mf++) {
            int row = warp_m * 64 + mf * 16 + (lane & 15);
            uint32_t off = (uint32_t)(row * 128 + ks * 32 + ((lane >> 4) << 4));
            ldsm4(ah[mf], sb + AT_Q + SWZ128(off));
            ldsm4(al[mf], sb + AT_Q + SWZ128(off + 64));
        }
        uint32_t bh2[4][2], bl2[4][2];
#pragma unroll
        for (int np = 0; np < 2; np++) {
            int g = lane >> 3;
            int nn = warp_n * 32 + np * 16 + ((g >> 1) << 3) + (lane & 7);
            uint32_t off = (uint32_t)(nn * 128 + ks * 32 + ((g & 1) << 4));
            uint32_t r[4];
            ldsm4(r, sb + AT_K + SWZ128(off));
            bh2[np * 2][0] = r[0]; bh2[np * 2][1] = r[1];
            bh2[np * 2 + 1][0] = r[2]; bh2[np * 2 + 1][1] = r[3];
            ldsm4(r, sb + AT_K + SWZ128(off + 64));
            bl2[np * 2][0] = r[0]; bl2[np * 2][1] = r[1];
            bl2[np * 2 + 1][0] = r[2]; bl2[np * 2 + 1][1] = r[3];
        }
#pragma unroll
        for (int mf = 0; mf < 4; mf++)
#pragma unroll
            for (int nf = 0; nf < 4; nf++) {
                mma16816(sc[mf][nf], ah[mf], bh2[nf]);
                mma16816(sc[mf][nf], ah[mf], bl2[nf]);
                mma16816(sc[mf][nf], al[mf], bh2[nf]);
            }
    }

    const float* bb = attn_bias + ((size_t)(b * NHEAD + h)) * MAXN * MAXN;
#pragma unroll
    for (int mf = 0; mf < 4; mf++) {
        int r0 = warp_m * 64 + mf * 16 + (lane >> 2);
#pragma unroll
        for (int nf = 0; nf < 4; nf++) {
            int c0 = warp_n * 32 + nf * 8 + (lane & 3) * 2;
#pragma unroll
            for (int hh = 0; hh < 2; hh++) {
                int r = r0 + hh * 8;
                float2 bv = *reinterpret_cast<const float2*>(&bb[r * MAXN + c0]);
                float v0 = sc[mf][nf][hh * 2] * ATT_SCALE + bv.x;
                float v1 = sc[mf][nf][hh * 2 + 1] * ATT_SCALE + bv.y;
                if (c0 >= n) v0 = -1e30f;
                if (c0 + 1 >= n) v1 = -1e30f;
                sc[mf][nf][hh * 2] = v0;
                sc[mf][nf][hh * 2 + 1] = v1;
            }
        }
    }

#pragma unroll
    for (int mf = 0; mf < 4; mf++)
#pragma unroll
        for (int hh = 0; hh < 2; hh++) {
            float mx = -1e30f;
#pragma unroll
            for (int nf = 0; nf < 4; nf++)
                mx = fmaxf(mx, fmaxf(sc[mf][nf][hh * 2], sc[mf][nf][hh * 2 + 1]));
            mx = fmaxf(mx, __shfl_xor_sync(0xffffffffu, mx, 1));
            mx = fmaxf(mx, __shfl_xor_sync(0xffffffffu, mx, 2));
            int row = warp_m * 64 + mf * 16 + (lane >> 2) + hh * 8;
            if ((lane & 3) == 0)
                *reinterpret_cast<float*>(sm + AT_PMAX + (row * 4 + warp_n) * 4) = mx;
        }
    __syncthreads();

#pragma unroll
    for (int mf = 0; mf < 4; mf++)
#pragma unroll
        for (int hh = 0; hh < 2; hh++) {
            int row = warp_m * 64 + mf * 16 + (lane >> 2) + hh * 8;
            float4 m4 = *reinterpret_cast<float4*>(sm + AT_PMAX + row * 16);
            float m = fmaxf(fmaxf(m4.x, m4.y), fmaxf(m4.z, m4.w));
            float ssum = 0.f;
#pragma unroll
            for (int nf = 0; nf < 4; nf++) {
                float p0 = __expf(sc[mf][nf][hh * 2] - m);
                float p1 = __expf(sc[mf][nf][hh * 2 + 1] - m);
                ssum += p0 + p1;
                int c0 = warp_n * 32 + nf * 8 + (lane & 3) * 2;
                __half h0, h1, l0, l1;
                split2(p0, h0, l0); split2(p1, h1, l1);
                uint32_t off = (uint32_t)(row * 256 + c0 * 2);
                *reinterpret_cast<uint32_t*>(sm + AT_PHI + SWZ256(off)) = packh(h0, h1);
                *reinterpret_cast<uint32_t*>(sm + AT_PLO + SWZ256(off)) = packh(l0, l1);
            }
            ssum += __shfl_xor_sync(0xffffffffu, ssum, 1);
            ssum += __shfl_xor_sync(0xffffffffu, ssum, 2);
            if ((lane & 3) == 0)
                *reinterpret_cast<float*>(sm + AT_PSUM + (row * 4 + warp_n) * 4) = ssum;
        }
    __syncthreads();

    if (tid < 128) {
        float4 s4 = *reinterpret_cast<float4*>(sm + AT_PSUM + tid * 16);
        float l = s4.x + s4.y + s4.z + s4.w;
        *reinterpret_cast<float*>(sm + AT_LINV + tid * 4) = 1.f / l;
    }
    __syncthreads();

    float oc[4][4];
#pragma unroll
    for (int j = 0; j < 4; j++)
#pragma unroll
        for (int k = 0; k < 4; k++) oc[j][k] = 0.f;

#pragma unroll
    for (int ks = 0; ks < 8; ks++) {
        uint32_t ph[4], pl[4];
        {
            int row = wid * 16 + (lane & 15);
            uint32_t off = (uint32_t)(row * 256 + ks * 32 + ((lane >> 4) << 4));
            ldsm4(ph, sb + AT_PHI + SWZ256(off));
            ldsm4(pl, sb + AT_PLO + SWZ256(off));
        }
        uint32_t vh[4][2], vl[4][2];
#pragma unroll
        for (int np = 0; np < 2; np++) {
            int g = lane >> 3;
            int nn = np * 16 + ((g >> 1) << 3) + (lane & 7);
            uint32_t off = (uint32_t)(nn * 256 + ks * 32 + ((g & 1) << 4));
            uint32_t r[4];
            ldsm4(r, sb + AT_VTHI + SWZ256(off));
            vh[np * 2][0] = r[0]; vh[np * 2][1] = r[1];
            vh[np * 2 + 1][0] = r[2]; vh[np * 2 + 1][1] = r[3];
            ldsm4(r, sb + AT_VTLO + SWZ256(off));
            vl[np * 2][0] = r[0]; vl[np * 2][1] = r[1];
            vl[np * 2 + 1][0] = r[2]; vl[np * 2 + 1][1] = r[3];
        }
#pragma unroll
        for (int nf = 0; nf < 4; nf++) {
            mma16816(oc[nf], ph, vh[nf]);
            mma16816(oc[nf], ph, vl[nf]);
            mma16816(oc[nf], pl, vh[nf]);
        }
    }

    int r0 = wid * 16 + (lane >> 2);
#pragma unroll
    for (int hh = 0; hh < 2; hh++) {
        int row = r0 + hh * 8;
        if (row >= n) continue;
        float linv = *reinterpret_cast<float*>(sm + AT_LINV + row * 4);
        size_t base = (size_t)(s0 + row) * D + h * HS;
#pragma unroll
        for (int nf = 0; nf < 4; nf++) {
            int d0 = nf * 8 + (lane & 3) * 2;
            float o0 = oc[nf][hh * 2] * linv;
            float o1 = oc[nf][hh * 2 + 1] * linv;
            __half h0, h1, l0, l1;
            split2(o0, h0, l0); split2(o1, h1, l1);
            *reinterpret_cast<uint32_t*>(&g_ahi[base + d0]) = packh(h0, h1);
            *reinterpret_cast<uint32_t*>(&g_alo[base + d0]) = packh(l0, l1);
        }
    }
}

// ---------------------------------------------------------------------------
// LayerNorm
// ---------------------------------------------------------------------------
__global__ void __launch_bounds__(256)
ln_kernel(const float* __restrict__ ln_w, const float* __restrict__ ln_b,
          float* __restrict__ out) {
    int row = blockIdx.x;
    const float* y = g_y + (size_t)row * D;
    int tid = threadIdx.x;

    float v0 = y[tid];
    float v1 = y[tid + 256];
    float s = v0 + v1;
    float q = v0 * v0 + v1 * v1;
#pragma unroll
    for (int off = 16; off; off >>= 1) {
        s += __shfl_down_sync(0xffffffffu, s, off);
        q += __shfl_down_sync(0xffffffffu, q, off);
    }
    __shared__ float rs[8], rq[8];
    __shared__ float s_mu, s_rstd;
    if ((tid & 31) == 0) { rs[tid >> 5] = s; rq[tid >> 5] = q; }
    __syncthreads();
    if (tid == 0) {
        float S = 0.f, Q = 0.f;
#pragma unroll
        for (int i = 0; i < 8; i++) { S += rs[i]; Q += rq[i]; }
        float mu = S * (1.f / D);
        float var = Q * (1.f / D) - mu * mu;
        s_mu = mu;
        s_rstd = rsqrtf(var + LN_EPS);
    }
    __syncthreads();
    float mu = s_mu, r = s_rstd;
    out[(size_t)row * D + tid] = (v0 - mu) * r * ln_w[tid] + ln_b[tid];
    out[(size_t)row * D + tid + 256] =
        (v1 - mu) * r * ln_w[tid + 256] + ln_b[tid + 256];
}

// ---------------------------------------------------------------------------
extern "C" void kernel_launch(void* const* d_in, const int* in_sizes, int n_in,
                              void* d_out, int out_size) {
    const float* x         = (const float*)d_in[0];
    const float* attn_bias = (const float*)d_in[1];
    const float* Wq = (const float*)d_in[2];
    const float* bq = (const float*)d_in[3];
    const float* Wk = (const float*)d_in[4];
    const float* bk = (const float*)d_in[5];
    const float* Wv = (const float*)d_in[6];
    const float* bv = (const float*)d_in[7];
    const float* Wp = (const float*)d_in[8];
    const float* bp = (const float*)d_in[9];
    const float* ln_w = (const float*)d_in[10];
    const float* ln_b = (const float*)d_in[11];
    const int*   batch = (const int*)d_in[12];

    int N = in_sizes[12];
    float* out = (float*)d_out;

    float *yp;
    __half *whi, *ahi, *qhi, *qlo, *khi, *klo, *vhi, *vlo, *alo;
    cudaGetSymbolAddress((void**)&yp, g_y);
    cudaGetSymbolAddress((void**)&whi, g_whi);
    cudaGetSymbolAddress((void**)&ahi, g_ahi);
    cudaGetSymbolAddress((void**)&alo, g_alo);
    cudaGetSymbolAddress((void**)&qhi, g_qhi);
    cudaGetSymbolAddress((void**)&qlo, g_qlo);
    cudaGetSymbolAddress((void**)&khi, g_khi);
    cudaGetSymbolAddress((void**)&klo, g_klo);
    cudaGetSymbolAddress((void**)&vhi, g_vhi);
    cudaGetSymbolAddress((void**)&vlo, g_vlo);

    const int smem_qkv = 3 * (128 * 128 + 128 * 128);   // 98304
    const int smem_prj = 3 * (64 * 128 + 128 * 128);    // 73728
    cudaFuncSetAttribute(mma_gemm<128, 1>,
                         cudaFuncAttributeMaxDynamicSharedMemorySize, smem_qkv);
    cudaFuncSetAttribute(mma_gemm<64, 0>,
                         cudaFuncAttributeMaxDynamicSharedMemorySize, smem_prj);
    cudaFuncSetAttribute(attn_mma,
                         cudaFuncAttributeMaxDynamicSharedMemorySize, AT_SMEM);

    // Fused prologue: split x, split W, segment starts
    int n4 = N * D / 4;
    int total = n4 + 4 * WELEM / 4 + N;
    prep_kernel<<<(total + 255) / 256, 256>>>(x, Wq, Wk, Wv, Wp, batch, N);

    // Fused QKV: grid.y 0-3 -> Wq, 4-7 -> Wk, 8-11 -> Wv
    mma_gemm<128, 1><<<dim3((N + 127) / 128, 12), 256, smem_qkv>>>(
        ahi, whi, WELEM, bq, bk, bv, nullptr,
        qhi, qlo, khi, klo, vhi, vlo, nullptr, N);

    attn_mma<<<NB * NHEAD, 256, AT_SMEM>>>(attn_bias);

    // Output projection + bias + residual (W plane 3)
    mma_gemm<64, 0><<<dim3((N + 63) / 64, 4), 256, smem_prj>>>(
        ahi, whi + 3 * WELEM, 0,
        bp, bp, bp, yp,
        nullptr, nullptr, nullptr, nullptr, nullptr, nullptr, x, N);

    ln_kernel<<<N, 256>>>(ln_w, ln_b, out);
}